// round 4
// baseline (speedup 1.0000x reference)
#include <cuda_runtime.h>
#include <cstdint>

// Problem constants (fixed by the dataset)
#define BB 2
#define SS 2048
#define DD 1024
#define HH 16
#define DK 64
#define MM (BB * SS)  // 4096 rows

// Scratch (allocation-free rule: __device__ globals)
__device__ float g_q[(size_t)BB * HH * SS * DK];    // (B,H,S,DK)
__device__ float g_k[(size_t)BB * HH * SS * DK];
__device__ float g_v[(size_t)BB * HH * SS * DK];
__device__ float g_ctx[(size_t)BB * SS * DD];       // (B,S,D)

// ---------------------------------------------------------------------------
// tf32 helpers (baseline sm_80+ ISA — no 'a'-suffix features)
// ---------------------------------------------------------------------------
__device__ __forceinline__ uint32_t f2tf32(float x) {
    uint32_t r;
    asm("cvt.rna.tf32.f32 %0, %1;" : "=r"(r) : "f"(x));
    return r;
}

__device__ __forceinline__ void mma_tf32(float c[4], const uint32_t a[4],
                                         const uint32_t b[2]) {
    asm volatile(
        "mma.sync.aligned.m16n8k8.row.col.f32.tf32.tf32.f32 "
        "{%0,%1,%2,%3}, {%4,%5,%6,%7}, {%8,%9}, {%0,%1,%2,%3};"
        : "+f"(c[0]), "+f"(c[1]), "+f"(c[2]), "+f"(c[3])
        : "r"(a[0]), "r"(a[1]), "r"(a[2]), "r"(a[3]), "r"(b[0]), "r"(b[1]));
}

// ---------------------------------------------------------------------------
// tf32 mma.sync GEMM: C[128,128] = A[128,1024] * W[128,1024]^T + bias
// 8 warps (2 m x 4 n), warp tile 64x32, BK=32, double-buffered smem.
// Smem holds fragment-PACKED tf32 tiles:
//   A slot (kt,mt,lane) -> float4 {a0,a1,a2,a3}   : byte ((kt*8+mt)*32+lane)*16
//   B slot (kt,nt,lane) -> float2 {b0,b1}         : byte 16384 + ((kt*16+nt)*32+lane)*8
// Buffers at buf*32768; total dynamic smem 64KB.
// ---------------------------------------------------------------------------
#define MM_SMEM_BYTES 65536

template <bool SCATTER>
__device__ __forceinline__ void mm_core(const float* __restrict__ A,
                                        const float* __restrict__ W,
                                        const float* __restrict__ bias,
                                        float* __restrict__ out,
                                        int m0, int n0) {
    extern __shared__ char smem[];
    const int tid = threadIdx.x;
    const int lane = tid & 31;
    const int wid = tid >> 5;
    const int warp_m = wid & 1;    // 0..1  (64 rows each)
    const int warp_n = wid >> 1;   // 0..3  (32 cols each)

    // Staging index (same for A and B): idx = tid + i*256; row=idx>>3; k4=idx&7
    // Each thread loads 4 float4 of A and 4 float4 of B per 128x32 chunk.
    float c[4][4][4];
#pragma unroll
    for (int i = 0; i < 4; i++)
#pragma unroll
        for (int j = 0; j < 4; j++)
#pragma unroll
            for (int e = 0; e < 4; e++) c[i][j][e] = 0.0f;

    const float* Abase = A + (size_t)m0 * DD;
    const float* Wbase = W + (size_t)n0 * DD;

    float4 av[4], bv[4];

    // ---- packed store helpers (as lambdas via macros) ----
#define STORE_STAGE(bufp)                                                     \
    do {                                                                      \
        char* sbA = smem + (bufp) * 32768;                                    \
        char* sbB = sbA + 16384;                                              \
        _Pragma("unroll") for (int i = 0; i < 4; i++) {                       \
            const int idx = tid + i * 256;                                    \
            const int row = idx >> 3, k4 = idx & 7;                           \
            const int kt = k4 >> 1, khi = k4 & 1;                             \
            { /* A pack */                                                    \
                const int mt = row >> 4, rm = row & 15;                       \
                char* base = sbA + (((kt * 8 + mt) * 32 + (rm & 7) * 4) << 4) \
                             + (((rm >> 3) + (khi << 1)) << 2);               \
                *(uint32_t*)(base + 0)  = f2tf32(av[i].x);                    \
                *(uint32_t*)(base + 16) = f2tf32(av[i].y);                    \
                *(uint32_t*)(base + 32) = f2tf32(av[i].z);                    \
                *(uint32_t*)(base + 48) = f2tf32(av[i].w);                    \
            }                                                                 \
            { /* B pack */                                                    \
                const int nt = row >> 3, rn = row & 7;                        \
                char* base = sbB + (((kt * 16 + nt) * 32 + rn * 4) << 3)      \
                             + (khi << 2);                                    \
                *(uint32_t*)(base + 0)  = f2tf32(bv[i].x);                    \
                *(uint32_t*)(base + 8)  = f2tf32(bv[i].y);                    \
                *(uint32_t*)(base + 16) = f2tf32(bv[i].z);                    \
                *(uint32_t*)(base + 24) = f2tf32(bv[i].w);                    \
            }                                                                 \
        }                                                                     \
    } while (0)

#define LOAD_STAGE(c0)                                                        \
    do {                                                                      \
        _Pragma("unroll") for (int i = 0; i < 4; i++) {                       \
            const int idx = tid + i * 256;                                    \
            const int row = idx >> 3, k4 = idx & 7;                           \
            av[i] = *(const float4*)(Abase + (size_t)row * DD + (c0) + k4 * 4); \
            bv[i] = *(const float4*)(Wbase + (size_t)row * DD + (c0) + k4 * 4); \
        }                                                                     \
    } while (0)

    // Prologue: chunk 0
    LOAD_STAGE(0);
    STORE_STAGE(0);
    __syncthreads();

    for (int ch = 0; ch < 32; ++ch) {
        const int buf = ch & 1;
        if (ch + 1 < 32) LOAD_STAGE((ch + 1) * 32);

        // Compute chunk ch from smem[buf]
        const char* sbA = smem + buf * 32768;
        const char* sbB = sbA + 16384;
#pragma unroll
        for (int kt = 0; kt < 4; ++kt) {
            uint32_t af[4][4];
            uint32_t bf[4][2];
#pragma unroll
            for (int i = 0; i < 4; ++i) {
                const float4 v = *(const float4*)(sbA +
                    (((kt * 8 + warp_m * 4 + i) * 32 + lane) << 4));
                af[i][0] = __float_as_uint(v.x);
                af[i][1] = __float_as_uint(v.y);
                af[i][2] = __float_as_uint(v.z);
                af[i][3] = __float_as_uint(v.w);
            }
#pragma unroll
            for (int j = 0; j < 4; ++j) {
                const float2 v = *(const float2*)(sbB +
                    (((kt * 16 + warp_n * 4 + j) * 32 + lane) << 3));
                bf[j][0] = __float_as_uint(v.x);
                bf[j][1] = __float_as_uint(v.y);
            }
#pragma unroll
            for (int i = 0; i < 4; ++i)
#pragma unroll
                for (int j = 0; j < 4; ++j) mma_tf32(c[i][j], af[i], bf[j]);
        }
        __syncthreads();
        if (ch + 1 < 32) {
            STORE_STAGE(buf ^ 1);
            __syncthreads();
        }
    }

    // Epilogue: c[i][j] covers rows warp_m*64+i*16+{lane>>2, +8},
    // cols warp_n*32+j*8+2*(lane&3)+{0,1}
#pragma unroll
    for (int i = 0; i < 4; ++i) {
        const int r0 = m0 + warp_m * 64 + i * 16 + (lane >> 2);
#pragma unroll
        for (int j = 0; j < 4; ++j) {
            const int cb = n0 + warp_n * 32 + j * 8 + 2 * (lane & 3);
            const float b0 = bias[cb], b1 = bias[cb + 1];
            float2 lo = {c[i][j][0] + b0, c[i][j][1] + b1};
            float2 hi = {c[i][j][2] + b0, c[i][j][3] + b1};
            if (SCATTER) {
                const int h = cb >> 6, d = cb & 63;
                const int bA = r0 >> 11, s0 = r0 & 2047;
                float* p0 = out + (((size_t)(bA * HH + h)) * SS + s0) * DK + d;
                *(float2*)p0 = lo;
                const int r1 = r0 + 8;
                const int bB = r1 >> 11, s1 = r1 & 2047;
                float* p1 = out + (((size_t)(bB * HH + h)) * SS + s1) * DK + d;
                *(float2*)p1 = hi;
            } else {
                *(float2*)(out + (size_t)r0 * DD + cb) = lo;
                *(float2*)(out + (size_t)(r0 + 8) * DD + cb) = hi;
            }
        }
    }
#undef STORE_STAGE
#undef LOAD_STAGE
}

__global__ void __launch_bounds__(256) qkv_mm_kernel(
    const float* __restrict__ x,
    const float* __restrict__ Wq, const float* __restrict__ bq,
    const float* __restrict__ Wk, const float* __restrict__ bk,
    const float* __restrict__ Wv, const float* __restrict__ bv) {
    const int z = blockIdx.z;
    const float* W = (z == 0) ? Wq : (z == 1) ? Wk : Wv;
    const float* bias = (z == 0) ? bq : (z == 1) ? bk : bv;
    float* out = (z == 0) ? g_q : (z == 1) ? g_k : g_v;
    mm_core<true>(x, W, bias, out, blockIdx.y * 128, blockIdx.x * 128);
}

__global__ void __launch_bounds__(256) oproj_mm_kernel(
    const float* __restrict__ Wo, const float* __restrict__ bo,
    float* __restrict__ out) {
    mm_core<false>(g_ctx, Wo, bo, out, blockIdx.y * 128, blockIdx.x * 128);
}

// ---------------------------------------------------------------------------
// Flash-style attention (unchanged; next optimization target).
// ---------------------------------------------------------------------------
__global__ void __launch_bounds__(128) attn_kernel(const int* __restrict__ mask) {
    __shared__ float ks[64 * 64];
    __shared__ float vs[64 * 64];
    __shared__ int msk[64];

    const int t = threadIdx.x;
    const int bh = blockIdx.y;
    const int b = bh >> 4;
    const int h = bh & 15;
    const int qs = blockIdx.x * 128 + t;

    const float* qp = g_q + ((size_t)bh * SS + qs) * DK;
    float q[64];
#pragma unroll
    for (int i = 0; i < 16; i++) {
        float4 v4 = ((const float4*)qp)[i];
        q[4 * i + 0] = v4.x; q[4 * i + 1] = v4.y;
        q[4 * i + 2] = v4.z; q[4 * i + 3] = v4.w;
    }

    float O[64];
#pragma unroll
    for (int d = 0; d < 64; d++) O[d] = 0.0f;
    float mrow = -1e30f;
    float l = 0.0f;

    const float* kbase = g_k + (size_t)bh * SS * DK;
    const float* vbase = g_v + (size_t)bh * SS * DK;

    for (int kt = 0; kt < SS / 64; kt++) {
        __syncthreads();
        const float4* ksrc = (const float4*)(kbase + (size_t)kt * 64 * 64);
        const float4* vsrc = (const float4*)(vbase + (size_t)kt * 64 * 64);
#pragma unroll
        for (int i = 0; i < 8; i++) {
            ((float4*)ks)[t + i * 128] = ksrc[t + i * 128];
            ((float4*)vs)[t + i * 128] = vsrc[t + i * 128];
        }
        if (t < 64) msk[t] = mask[b * SS + kt * 64 + t];
        __syncthreads();

#pragma unroll 1
        for (int j = 0; j < 64; j++) {
            const float4* kj = (const float4*)(ks + j * 64);
            float s = 0.0f;
#pragma unroll
            for (int d4 = 0; d4 < 16; d4++) {
                float4 kk = kj[d4];
                s += q[4 * d4 + 0] * kk.x + q[4 * d4 + 1] * kk.y +
                     q[4 * d4 + 2] * kk.z + q[4 * d4 + 3] * kk.w;
            }
            s *= 0.125f;
            if (msk[j] == 0) s = -1e9f;

            if (s > mrow) {
                const float corr = __expf(mrow - s);
                l *= corr;
#pragma unroll
                for (int d = 0; d < 64; d++) O[d] *= corr;
                mrow = s;
            }
            const float p = __expf(s - mrow);
            l += p;

            const float4* vj = (const float4*)(vs + j * 64);
#pragma unroll
            for (int d4 = 0; d4 < 16; d4++) {
                float4 vv = vj[d4];
                O[4 * d4 + 0] += p * vv.x;
                O[4 * d4 + 1] += p * vv.y;
                O[4 * d4 + 2] += p * vv.z;
                O[4 * d4 + 3] += p * vv.w;
            }
        }
    }

    const float inv = 1.0f / l;
    float* op = g_ctx + ((size_t)(b * SS + qs)) * DD + h * DK;
#pragma unroll
    for (int i = 0; i < 16; i++) {
        float4 o4;
        o4.x = O[4 * i + 0] * inv;
        o4.y = O[4 * i + 1] * inv;
        o4.z = O[4 * i + 2] * inv;
        o4.w = O[4 * i + 3] * inv;
        ((float4*)op)[i] = o4;
    }
}

// ---------------------------------------------------------------------------
// Inputs (metadata order): x, mask, Wq, bq, Wk, bk, Wv, bv, Wo, bo
// ---------------------------------------------------------------------------
extern "C" void kernel_launch(void* const* d_in, const int* in_sizes, int n_in,
                              void* d_out, int out_size) {
    const float* x  = (const float*)d_in[0];
    const int*   mk = (const int*)d_in[1];
    const float* Wq = (const float*)d_in[2];
    const float* bq = (const float*)d_in[3];
    const float* Wk = (const float*)d_in[4];
    const float* bk = (const float*)d_in[5];
    const float* Wv = (const float*)d_in[6];
    const float* bv = (const float*)d_in[7];
    const float* Wo = (const float*)d_in[8];
    const float* bo = (const float*)d_in[9];
    float* out = (float*)d_out;

    static bool configured = false;
    if (!configured) {
        cudaFuncSetAttribute(qkv_mm_kernel,
                             cudaFuncAttributeMaxDynamicSharedMemorySize,
                             MM_SMEM_BYTES);
        cudaFuncSetAttribute(oproj_mm_kernel,
                             cudaFuncAttributeMaxDynamicSharedMemorySize,
                             MM_SMEM_BYTES);
        configured = true;
    }

    // QKV projections (tf32 mma.sync), scattered to (B,H,S,DK)
    qkv_mm_kernel<<<dim3(DD / 128, MM / 128, 3), 256, MM_SMEM_BYTES>>>(
        x, Wq, bq, Wk, bk, Wv, bv);

    // Attention: 16 q-blocks of 128 rows x 32 (b,h) pairs
    attn_kernel<<<dim3(SS / 128, BB * HH), 128>>>(mk);

    // Output projection (tf32 mma.sync) -> d_out
    oproj_mm_kernel<<<dim3(DD / 128, MM / 128), 256, MM_SMEM_BYTES>>>(Wo, bo, out);
}

// round 5
// speedup vs baseline: 1.7200x; 1.7200x over previous
#include <cuda_runtime.h>
#include <cstdint>

// Problem constants (fixed by the dataset)
#define BB 2
#define SS 2048
#define DD 1024
#define HH 16
#define DK 64
#define MM (BB * SS)  // 4096 rows

// Scratch (allocation-free rule: __device__ globals)
__device__ float g_q[(size_t)BB * HH * SS * DK];    // (B,H,S,DK)
__device__ float g_k[(size_t)BB * HH * SS * DK];
__device__ float g_v[(size_t)BB * HH * SS * DK];
__device__ float g_ctx[(size_t)BB * SS * DD];       // (B,S,D)

// ---------------------------------------------------------------------------
// tf32 helpers (baseline sm_80+ ISA — no 'a'-suffix features)
// ---------------------------------------------------------------------------
__device__ __forceinline__ uint32_t f2tf32(float x) {
    uint32_t r;
    asm("cvt.rna.tf32.f32 %0, %1;" : "=r"(r) : "f"(x));
    return r;
}

__device__ __forceinline__ void mma_tf32(float c[4], const uint32_t a[4],
                                         const uint32_t b[2]) {
    asm volatile(
        "mma.sync.aligned.m16n8k8.row.col.f32.tf32.tf32.f32 "
        "{%0,%1,%2,%3}, {%4,%5,%6,%7}, {%8,%9}, {%0,%1,%2,%3};"
        : "+f"(c[0]), "+f"(c[1]), "+f"(c[2]), "+f"(c[3])
        : "r"(a[0]), "r"(a[1]), "r"(a[2]), "r"(a[3]), "r"(b[0]), "r"(b[1]));
}

// ---------------------------------------------------------------------------
// tf32 mma.sync GEMM: C[128,128] = A[128,1024] * W[128,1024]^T + bias
// (unchanged from round 4; 8 warps, warp tile 64x32, BK=32, double-buffered)
// ---------------------------------------------------------------------------
#define MM_SMEM_BYTES 65536

template <bool SCATTER>
__device__ __forceinline__ void mm_core(const float* __restrict__ A,
                                        const float* __restrict__ W,
                                        const float* __restrict__ bias,
                                        float* __restrict__ out,
                                        int m0, int n0) {
    extern __shared__ char smem[];
    const int tid = threadIdx.x;
    const int lane = tid & 31;
    const int wid = tid >> 5;
    const int warp_m = wid & 1;
    const int warp_n = wid >> 1;

    float c[4][4][4];
#pragma unroll
    for (int i = 0; i < 4; i++)
#pragma unroll
        for (int j = 0; j < 4; j++)
#pragma unroll
            for (int e = 0; e < 4; e++) c[i][j][e] = 0.0f;

    const float* Abase = A + (size_t)m0 * DD;
    const float* Wbase = W + (size_t)n0 * DD;

    float4 av[4], bv[4];

#define STORE_STAGE(bufp)                                                     \
    do {                                                                      \
        char* sbA = smem + (bufp) * 32768;                                    \
        char* sbB = sbA + 16384;                                              \
        _Pragma("unroll") for (int i = 0; i < 4; i++) {                       \
            const int idx = tid + i * 256;                                    \
            const int row = idx >> 3, k4 = idx & 7;                           \
            const int kt = k4 >> 1, khi = k4 & 1;                             \
            {                                                                 \
                const int mt = row >> 4, rm = row & 15;                       \
                char* base = sbA + (((kt * 8 + mt) * 32 + (rm & 7) * 4) << 4) \
                             + (((rm >> 3) + (khi << 1)) << 2);               \
                *(uint32_t*)(base + 0)  = f2tf32(av[i].x);                    \
                *(uint32_t*)(base + 16) = f2tf32(av[i].y);                    \
                *(uint32_t*)(base + 32) = f2tf32(av[i].z);                    \
                *(uint32_t*)(base + 48) = f2tf32(av[i].w);                    \
            }                                                                 \
            {                                                                 \
                const int nt = row >> 3, rn = row & 7;                        \
                char* base = sbB + (((kt * 16 + nt) * 32 + rn * 4) << 3)      \
                             + (khi << 2);                                    \
                *(uint32_t*)(base + 0)  = f2tf32(bv[i].x);                    \
                *(uint32_t*)(base + 8)  = f2tf32(bv[i].y);                    \
                *(uint32_t*)(base + 16) = f2tf32(bv[i].z);                    \
                *(uint32_t*)(base + 24) = f2tf32(bv[i].w);                    \
            }                                                                 \
        }                                                                     \
    } while (0)

#define LOAD_STAGE(c0)                                                        \
    do {                                                                      \
        _Pragma("unroll") for (int i = 0; i < 4; i++) {                       \
            const int idx = tid + i * 256;                                    \
            const int row = idx >> 3, k4 = idx & 7;                           \
            av[i] = *(const float4*)(Abase + (size_t)row * DD + (c0) + k4 * 4); \
            bv[i] = *(const float4*)(Wbase + (size_t)row * DD + (c0) + k4 * 4); \
        }                                                                     \
    } while (0)

    LOAD_STAGE(0);
    STORE_STAGE(0);
    __syncthreads();

    for (int ch = 0; ch < 32; ++ch) {
        const int buf = ch & 1;
        if (ch + 1 < 32) LOAD_STAGE((ch + 1) * 32);

        const char* sbA = smem + buf * 32768;
        const char* sbB = sbA + 16384;
#pragma unroll
        for (int kt = 0; kt < 4; ++kt) {
            uint32_t af[4][4];
            uint32_t bf[4][2];
#pragma unroll
            for (int i = 0; i < 4; ++i) {
                const float4 v = *(const float4*)(sbA +
                    (((kt * 8 + warp_m * 4 + i) * 32 + lane) << 4));
                af[i][0] = __float_as_uint(v.x);
                af[i][1] = __float_as_uint(v.y);
                af[i][2] = __float_as_uint(v.z);
                af[i][3] = __float_as_uint(v.w);
            }
#pragma unroll
            for (int j = 0; j < 4; ++j) {
                const float2 v = *(const float2*)(sbB +
                    (((kt * 16 + warp_n * 4 + j) * 32 + lane) << 3));
                bf[j][0] = __float_as_uint(v.x);
                bf[j][1] = __float_as_uint(v.y);
            }
#pragma unroll
            for (int i = 0; i < 4; ++i)
#pragma unroll
                for (int j = 0; j < 4; ++j) mma_tf32(c[i][j], af[i], bf[j]);
        }
        __syncthreads();
        if (ch + 1 < 32) {
            STORE_STAGE(buf ^ 1);
            __syncthreads();
        }
    }

#pragma unroll
    for (int i = 0; i < 4; ++i) {
        const int r0 = m0 + warp_m * 64 + i * 16 + (lane >> 2);
#pragma unroll
        for (int j = 0; j < 4; ++j) {
            const int cb = n0 + warp_n * 32 + j * 8 + 2 * (lane & 3);
            const float b0 = bias[cb], b1 = bias[cb + 1];
            float2 lo = {c[i][j][0] + b0, c[i][j][1] + b1};
            float2 hi = {c[i][j][2] + b0, c[i][j][3] + b1};
            if (SCATTER) {
                const int h = cb >> 6, d = cb & 63;
                const int bA = r0 >> 11, s0 = r0 & 2047;
                float* p0 = out + (((size_t)(bA * HH + h)) * SS + s0) * DK + d;
                *(float2*)p0 = lo;
                const int r1 = r0 + 8;
                const int bB = r1 >> 11, s1 = r1 & 2047;
                float* p1 = out + (((size_t)(bB * HH + h)) * SS + s1) * DK + d;
                *(float2*)p1 = hi;
            } else {
                *(float2*)(out + (size_t)r0 * DD + cb) = lo;
                *(float2*)(out + (size_t)(r0 + 8) * DD + cb) = hi;
            }
        }
    }
#undef STORE_STAGE
#undef LOAD_STAGE
}

__global__ void __launch_bounds__(256) qkv_mm_kernel(
    const float* __restrict__ x,
    const float* __restrict__ Wq, const float* __restrict__ bq,
    const float* __restrict__ Wk, const float* __restrict__ bk,
    const float* __restrict__ Wv, const float* __restrict__ bv) {
    const int z = blockIdx.z;
    const float* W = (z == 0) ? Wq : (z == 1) ? Wk : Wv;
    const float* bias = (z == 0) ? bq : (z == 1) ? bk : bv;
    float* out = (z == 0) ? g_q : (z == 1) ? g_k : g_v;
    mm_core<true>(x, W, bias, out, blockIdx.y * 128, blockIdx.x * 128);
}

__global__ void __launch_bounds__(256) oproj_mm_kernel(
    const float* __restrict__ Wo, const float* __restrict__ bo,
    float* __restrict__ out) {
    mm_core<false>(g_ctx, Wo, bo, out, blockIdx.y * 128, blockIdx.x * 128);
}

// ---------------------------------------------------------------------------
// Tensor-core flash attention.
// CTA: 128 q rows x one (b,h). 8 warps, 16 q rows each. 64-key tiles.
// QK^T: 3xTF32 (hi/lo split) -> ~fp32-accurate scores.
// Softmax in C-fragment registers (quad shfl reductions), online rescale.
// P -> per-warp smem (tf32-rounded) -> A-fragments; PV single-pass tf32.
//
// smem map (bytes):
//   KPH   = 0      : K hi pack, 16KB   (B-frag: n=key, k=d)
//   KPL   = 16384  : K lo pack, 16KB
//   VPK   = 32768  : V pack,    16KB   (B-frag: n=d, k=key)
//   MSKO  = 49152  : mask add,  256B
//   PO    = 49408  : P, 8 warps x 16 rows x 68 floats = 34816B
// ---------------------------------------------------------------------------
#define ATTN_SMEM 84480
#define KPH 0
#define KPL 16384
#define VPK 32768
#define MSKO 49152
#define PO 49408
#define PSTRIDE 68
#define PWARP 4352

__global__ void __launch_bounds__(256, 1) attn_kernel(const int* __restrict__ mask) {
    extern __shared__ char smem[];
    const int tid = threadIdx.x;
    const int lane = tid & 31;
    const int w = tid >> 5;
    const int gid = lane >> 2;   // group id (row within m16)
    const int tig = lane & 3;    // thread in group

    const int bh = blockIdx.y;
    const int b = bh >> 4;
    const int h = bh & 15;
    const int qs_base = blockIdx.x * 128 + w * 16;

    const float* qbase = g_q + (size_t)bh * SS * DK;
    const float* kbase = g_k + (size_t)bh * SS * DK;
    const float* vbase = g_v + (size_t)bh * SS * DK;

    // ---- Q fragments (scale 1/8 folded in, hi/lo tf32 split), resident ----
    uint32_t qh[8][4], ql[8][4];
#pragma unroll
    for (int kt = 0; kt < 8; ++kt) {
#pragma unroll
        for (int e = 0; e < 4; ++e) {
            const int r = qs_base + gid + (e & 1) * 8;
            const int d = kt * 8 + tig + (e >> 1) * 4;
            const float x = qbase[(size_t)r * DK + d] * 0.125f;
            const uint32_t hb = f2tf32(x);
            qh[kt][e] = hb;
            ql[kt][e] = f2tf32(x - __uint_as_float(hb));
        }
    }

    float o[8][4];
#pragma unroll
    for (int j = 0; j < 8; ++j)
#pragma unroll
        for (int e = 0; e < 4; ++e) o[j][e] = 0.0f;
    float m0 = -1e30f, m1 = -1e30f, l0 = 0.0f, l1 = 0.0f;

    char* Pw = smem + PO + w * PWARP;

    for (int t = 0; t < SS / 64; ++t) {
        const int key0 = t * 64;
        __syncthreads();
        // ---- stage K (hi/lo) and V into fragment-packed smem ----
#pragma unroll
        for (int i = 0; i < 4; ++i) {
            const int idx = tid + i * 256;     // 0..1023 float4 units
            const int row = idx >> 4;          // key within tile
            const int p4 = idx & 15;
            const float4 kv = *(const float4*)(kbase + (size_t)(key0 + row) * DK + p4 * 4);
            const float4 vv = *(const float4*)(vbase + (size_t)(key0 + row) * DK + p4 * 4);
            const float ke[4] = {kv.x, kv.y, kv.z, kv.w};
            const float ve[4] = {vv.x, vv.y, vv.z, vv.w};
#pragma unroll
            for (int e = 0; e < 4; ++e) {
                const int d = p4 * 4 + e;
                // K dest: slot(kt=d>>3, nt=row>>3), lane=(row&7)*4+(d&3), half=(d>>2)&1
                const int kbyte = (((d >> 3) * 8 + (row >> 3)) << 8) +
                                  ((row & 7) << 5) + ((d & 3) << 3) +
                                  (((d >> 2) & 1) << 2);
                const uint32_t hb = f2tf32(ke[e]);
                *(uint32_t*)(smem + KPH + kbyte) = hb;
                *(uint32_t*)(smem + KPL + kbyte) = f2tf32(ke[e] - __uint_as_float(hb));
                // V dest: slot(kt=row>>3, nt=d>>3), lane=(d&7)*4+(row&3), half=(row>>2)&1
                const int vbyte = (((row >> 3) * 8 + (d >> 3)) << 8) +
                                  ((d & 7) << 5) + ((row & 3) << 3) +
                                  (((row >> 2) & 1) << 2);
                *(uint32_t*)(smem + VPK + vbyte) = f2tf32(ve[e]);
            }
        }
        if (tid < 64)
            *(float*)(smem + MSKO + tid * 4) =
                mask[b * SS + key0 + tid] ? 0.0f : -1e9f;
        __syncthreads();

        // ---- scores: S = (Q/8) K^T via 3xTF32 ----
        float sc[8][4];
#pragma unroll
        for (int j = 0; j < 8; ++j)
#pragma unroll
            for (int e = 0; e < 4; ++e) sc[j][e] = 0.0f;
#pragma unroll
        for (int kt = 0; kt < 8; ++kt) {
#pragma unroll
            for (int j = 0; j < 8; ++j) {
                const int off = (((kt * 8 + j) * 32 + lane) << 3);
                uint32_t bhf[2], blf[2];
                const uint2 bh2 = *(const uint2*)(smem + KPH + off);
                const uint2 bl2 = *(const uint2*)(smem + KPL + off);
                bhf[0] = bh2.x; bhf[1] = bh2.y;
                blf[0] = bl2.x; blf[1] = bl2.y;
                mma_tf32(sc[j], qh[kt], bhf);
                mma_tf32(sc[j], qh[kt], blf);
                mma_tf32(sc[j], ql[kt], bhf);
            }
        }

        // ---- mask, online softmax ----
#pragma unroll
        for (int j = 0; j < 8; ++j) {
            const float2 ma = *(const float2*)(smem + MSKO + (j * 8 + 2 * tig) * 4);
            sc[j][0] += ma.x; sc[j][1] += ma.y;
            sc[j][2] += ma.x; sc[j][3] += ma.y;
        }
        float rm0 = -1e30f, rm1 = -1e30f;
#pragma unroll
        for (int j = 0; j < 8; ++j) {
            rm0 = fmaxf(rm0, fmaxf(sc[j][0], sc[j][1]));
            rm1 = fmaxf(rm1, fmaxf(sc[j][2], sc[j][3]));
        }
        rm0 = fmaxf(rm0, __shfl_xor_sync(0xFFFFFFFF, rm0, 1));
        rm0 = fmaxf(rm0, __shfl_xor_sync(0xFFFFFFFF, rm0, 2));
        rm1 = fmaxf(rm1, __shfl_xor_sync(0xFFFFFFFF, rm1, 1));
        rm1 = fmaxf(rm1, __shfl_xor_sync(0xFFFFFFFF, rm1, 2));
        const float nm0 = fmaxf(m0, rm0), nm1 = fmaxf(m1, rm1);
        const float c0 = __expf(m0 - nm0), c1 = __expf(m1 - nm1);
        m0 = nm0; m1 = nm1;
        l0 *= c0; l1 *= c1;
#pragma unroll
        for (int j = 0; j < 8; ++j) {
            o[j][0] *= c0; o[j][1] *= c0;
            o[j][2] *= c1; o[j][3] *= c1;
        }
        float s0 = 0.0f, s1 = 0.0f;
#pragma unroll
        for (int j = 0; j < 8; ++j) {
            const float p0 = __expf(sc[j][0] - nm0);
            const float p1 = __expf(sc[j][1] - nm0);
            const float p2 = __expf(sc[j][2] - nm1);
            const float p3 = __expf(sc[j][3] - nm1);
            s0 += p0 + p1; s1 += p2 + p3;
            const int cb = j * 8 + 2 * tig;
            float2 v0 = {__uint_as_float(f2tf32(p0)), __uint_as_float(f2tf32(p1))};
            float2 v1 = {__uint_as_float(f2tf32(p2)), __uint_as_float(f2tf32(p3))};
            *(float2*)(Pw + (gid * PSTRIDE + cb) * 4) = v0;
            *(float2*)(Pw + ((gid + 8) * PSTRIDE + cb) * 4) = v1;
        }
        l0 += s0; l1 += s1;
        __syncwarp();

        // ---- O += P V (tf32) ----
#pragma unroll
        for (int kk = 0; kk < 8; ++kk) {
            uint32_t pa[4];
            pa[0] = *(const uint32_t*)(Pw + (gid * PSTRIDE + kk * 8 + tig) * 4);
            pa[1] = *(const uint32_t*)(Pw + ((gid + 8) * PSTRIDE + kk * 8 + tig) * 4);
            pa[2] = *(const uint32_t*)(Pw + (gid * PSTRIDE + kk * 8 + tig + 4) * 4);
            pa[3] = *(const uint32_t*)(Pw + ((gid + 8) * PSTRIDE + kk * 8 + tig + 4) * 4);
#pragma unroll
            for (int j = 0; j < 8; ++j) {
                uint32_t bvf[2];
                const uint2 bv2 =
                    *(const uint2*)(smem + VPK + (((kk * 8 + j) * 32 + lane) << 3));
                bvf[0] = bv2.x; bvf[1] = bv2.y;
                mma_tf32(o[j], pa, bvf);
            }
        }
        __syncwarp();
    }

    // ---- finalize: full row sums across quad, normalize, store ----
    float lt0 = l0, lt1 = l1;
    lt0 += __shfl_xor_sync(0xFFFFFFFF, lt0, 1);
    lt0 += __shfl_xor_sync(0xFFFFFFFF, lt0, 2);
    lt1 += __shfl_xor_sync(0xFFFFFFFF, lt1, 1);
    lt1 += __shfl_xor_sync(0xFFFFFFFF, lt1, 2);
    const float inv0 = 1.0f / lt0, inv1 = 1.0f / lt1;

    const int r0 = qs_base + gid, r1 = r0 + 8;
    float* o0 = g_ctx + ((size_t)(b * SS + r0)) * DD + h * DK;
    float* o1 = g_ctx + ((size_t)(b * SS + r1)) * DD + h * DK;
#pragma unroll
    for (int j = 0; j < 8; ++j) {
        const int cb = j * 8 + 2 * tig;
        float2 v0 = {o[j][0] * inv0, o[j][1] * inv0};
        float2 v1 = {o[j][2] * inv1, o[j][3] * inv1};
        *(float2*)(o0 + cb) = v0;
        *(float2*)(o1 + cb) = v1;
    }
}

// ---------------------------------------------------------------------------
// Inputs (metadata order): x, mask, Wq, bq, Wk, bk, Wv, bv, Wo, bo
// ---------------------------------------------------------------------------
extern "C" void kernel_launch(void* const* d_in, const int* in_sizes, int n_in,
                              void* d_out, int out_size) {
    const float* x  = (const float*)d_in[0];
    const int*   mk = (const int*)d_in[1];
    const float* Wq = (const float*)d_in[2];
    const float* bq = (const float*)d_in[3];
    const float* Wk = (const float*)d_in[4];
    const float* bk = (const float*)d_in[5];
    const float* Wv = (const float*)d_in[6];
    const float* bv = (const float*)d_in[7];
    const float* Wo = (const float*)d_in[8];
    const float* bo = (const float*)d_in[9];
    float* out = (float*)d_out;

    static bool configured = false;
    if (!configured) {
        cudaFuncSetAttribute(qkv_mm_kernel,
                             cudaFuncAttributeMaxDynamicSharedMemorySize,
                             MM_SMEM_BYTES);
        cudaFuncSetAttribute(oproj_mm_kernel,
                             cudaFuncAttributeMaxDynamicSharedMemorySize,
                             MM_SMEM_BYTES);
        cudaFuncSetAttribute(attn_kernel,
                             cudaFuncAttributeMaxDynamicSharedMemorySize,
                             ATTN_SMEM);
        configured = true;
    }

    // QKV projections (tf32 mma.sync), scattered to (B,H,S,DK)
    qkv_mm_kernel<<<dim3(DD / 128, MM / 128, 3), 256, MM_SMEM_BYTES>>>(
        x, Wq, bq, Wk, bk, Wv, bv);

    // Tensor-core flash attention
    attn_kernel<<<dim3(SS / 128, BB * HH), 256, ATTN_SMEM>>>(mk);

    // Output projection (tf32 mma.sync) -> d_out
    oproj_mm_kernel<<<dim3(DD / 128, MM / 128), 256, MM_SMEM_BYTES>>>(Wo, bo, out);
}

// round 6
// speedup vs baseline: 2.8123x; 1.6351x over previous
#include <cuda_runtime.h>
#include <cstdint>

// Problem constants (fixed by the dataset)
#define BB 2
#define SS 2048
#define DD 1024
#define HH 16
#define DK 64
#define MM (BB * SS)  // 4096 rows

// Scratch (allocation-free rule: __device__ globals)
__device__ float g_q[(size_t)BB * HH * SS * DK];    // (B,H,S,DK)
__device__ float g_k[(size_t)BB * HH * SS * DK];
__device__ float g_v[(size_t)BB * HH * SS * DK];
__device__ float g_ctx[(size_t)BB * SS * DD];       // (B,S,D)

// ---------------------------------------------------------------------------
// tf32 helpers (baseline sm_80+ ISA — no 'a'-suffix features)
// ---------------------------------------------------------------------------
__device__ __forceinline__ uint32_t f2tf32(float x) {
    uint32_t r;
    asm("cvt.rna.tf32.f32 %0, %1;" : "=r"(r) : "f"(x));
    return r;
}

__device__ __forceinline__ void mma_tf32(float c[4], const uint32_t a[4],
                                         const uint32_t b[2]) {
    asm volatile(
        "mma.sync.aligned.m16n8k8.row.col.f32.tf32.tf32.f32 "
        "{%0,%1,%2,%3}, {%4,%5,%6,%7}, {%8,%9}, {%0,%1,%2,%3};"
        : "+f"(c[0]), "+f"(c[1]), "+f"(c[2]), "+f"(c[3])
        : "r"(a[0]), "r"(a[1]), "r"(a[2]), "r"(a[3]), "r"(b[0]), "r"(b[1]));
}

// ---------------------------------------------------------------------------
// tf32 mma.sync GEMM: C[128,128] = A[128,1024] * W[128,1024]^T + bias
// 8 warps (2 m x 4 n), warp tile 64x32, BK=32, double-buffered smem,
// single __syncthreads per K-chunk (STS(ch) ; LDG(ch+1) ; sync ; compute(ch)).
// ---------------------------------------------------------------------------
#define MM_SMEM_BYTES 65536

template <bool SCATTER>
__device__ __forceinline__ void mm_core(const float* __restrict__ A,
                                        const float* __restrict__ W,
                                        const float* __restrict__ bias,
                                        float* __restrict__ out,
                                        int m0, int n0) {
    extern __shared__ char smem[];
    const int tid = threadIdx.x;
    const int lane = tid & 31;
    const int wid = tid >> 5;
    const int warp_m = wid & 1;
    const int warp_n = wid >> 1;

    float c[4][4][4];
#pragma unroll
    for (int i = 0; i < 4; i++)
#pragma unroll
        for (int j = 0; j < 4; j++)
#pragma unroll
            for (int e = 0; e < 4; e++) c[i][j][e] = 0.0f;

    const float* Abase = A + (size_t)m0 * DD;
    const float* Wbase = W + (size_t)n0 * DD;

    float4 av[4], bv[4];

#define STORE_STAGE(bufp)                                                     \
    do {                                                                      \
        char* sbA = smem + (bufp) * 32768;                                    \
        char* sbB = sbA + 16384;                                              \
        _Pragma("unroll") for (int i = 0; i < 4; i++) {                       \
            const int idx = tid + i * 256;                                    \
            const int row = idx >> 3, k4 = idx & 7;                           \
            const int kt = k4 >> 1, khi = k4 & 1;                             \
            {                                                                 \
                const int mt = row >> 4, rm = row & 15;                       \
                char* base = sbA + (((kt * 8 + mt) * 32 + (rm & 7) * 4) << 4) \
                             + (((rm >> 3) + (khi << 1)) << 2);               \
                *(uint32_t*)(base + 0)  = f2tf32(av[i].x);                    \
                *(uint32_t*)(base + 16) = f2tf32(av[i].y);                    \
                *(uint32_t*)(base + 32) = f2tf32(av[i].z);                    \
                *(uint32_t*)(base + 48) = f2tf32(av[i].w);                    \
            }                                                                 \
            {                                                                 \
                const int nt = row >> 3, rn = row & 7;                        \
                char* base = sbB + (((kt * 16 + nt) * 32 + rn * 4) << 3)      \
                             + (khi << 2);                                    \
                *(uint32_t*)(base + 0)  = f2tf32(bv[i].x);                    \
                *(uint32_t*)(base + 8)  = f2tf32(bv[i].y);                    \
                *(uint32_t*)(base + 16) = f2tf32(bv[i].z);                    \
                *(uint32_t*)(base + 24) = f2tf32(bv[i].w);                    \
            }                                                                 \
        }                                                                     \
    } while (0)

#define LOAD_STAGE(c0)                                                        \
    do {                                                                      \
        _Pragma("unroll") for (int i = 0; i < 4; i++) {                       \
            const int idx = tid + i * 256;                                    \
            const int row = idx >> 3, k4 = idx & 7;                           \
            av[i] = *(const float4*)(Abase + (size_t)row * DD + (c0) + k4 * 4); \
            bv[i] = *(const float4*)(Wbase + (size_t)row * DD + (c0) + k4 * 4); \
        }                                                                     \
    } while (0)

    LOAD_STAGE(0);

    for (int ch = 0; ch < 32; ++ch) {
        const int buf = ch & 1;
        STORE_STAGE(buf);
        if (ch + 1 < 32) LOAD_STAGE((ch + 1) * 32);
        __syncthreads();

        const char* sbA = smem + buf * 32768;
        const char* sbB = sbA + 16384;
#pragma unroll
        for (int kt = 0; kt < 4; ++kt) {
            uint32_t af[4][4];
            uint32_t bf[4][2];
#pragma unroll
            for (int i = 0; i < 4; ++i) {
                const float4 v = *(const float4*)(sbA +
                    (((kt * 8 + warp_m * 4 + i) * 32 + lane) << 4));
                af[i][0] = __float_as_uint(v.x);
                af[i][1] = __float_as_uint(v.y);
                af[i][2] = __float_as_uint(v.z);
                af[i][3] = __float_as_uint(v.w);
            }
#pragma unroll
            for (int j = 0; j < 4; ++j) {
                const float2 v = *(const float2*)(sbB +
                    (((kt * 16 + warp_n * 4 + j) * 32 + lane) << 3));
                bf[j][0] = __float_as_uint(v.x);
                bf[j][1] = __float_as_uint(v.y);
            }
#pragma unroll
            for (int i = 0; i < 4; ++i)
#pragma unroll
                for (int j = 0; j < 4; ++j) mma_tf32(c[i][j], af[i], bf[j]);
        }
    }

#pragma unroll
    for (int i = 0; i < 4; ++i) {
        const int r0 = m0 + warp_m * 64 + i * 16 + (lane >> 2);
#pragma unroll
        for (int j = 0; j < 4; ++j) {
            const int cb = n0 + warp_n * 32 + j * 8 + 2 * (lane & 3);
            const float b0 = bias[cb], b1 = bias[cb + 1];
            float2 lo = {c[i][j][0] + b0, c[i][j][1] + b1};
            float2 hi = {c[i][j][2] + b0, c[i][j][3] + b1};
            if (SCATTER) {
                const int h = cb >> 6, d = cb & 63;
                const int bA = r0 >> 11, s0 = r0 & 2047;
                float* p0 = out + (((size_t)(bA * HH + h)) * SS + s0) * DK + d;
                *(float2*)p0 = lo;
                const int r1 = r0 + 8;
                const int bB = r1 >> 11, s1 = r1 & 2047;
                float* p1 = out + (((size_t)(bB * HH + h)) * SS + s1) * DK + d;
                *(float2*)p1 = hi;
            } else {
                *(float2*)(out + (size_t)r0 * DD + cb) = lo;
                *(float2*)(out + (size_t)(r0 + 8) * DD + cb) = hi;
            }
        }
    }
#undef STORE_STAGE
#undef LOAD_STAGE
}

__global__ void __launch_bounds__(256) qkv_mm_kernel(
    const float* __restrict__ x,
    const float* __restrict__ Wq, const float* __restrict__ bq,
    const float* __restrict__ Wk, const float* __restrict__ bk,
    const float* __restrict__ Wv, const float* __restrict__ bv) {
    const int z = blockIdx.z;
    const float* W = (z == 0) ? Wq : (z == 1) ? Wk : Wv;
    const float* bias = (z == 0) ? bq : (z == 1) ? bk : bv;
    float* out = (z == 0) ? g_q : (z == 1) ? g_k : g_v;
    mm_core<true>(x, W, bias, out, blockIdx.y * 128, blockIdx.x * 128);
}

__global__ void __launch_bounds__(256) oproj_mm_kernel(
    const float* __restrict__ Wo, const float* __restrict__ bo,
    float* __restrict__ out) {
    mm_core<false>(g_ctx, Wo, bo, out, blockIdx.y * 128, blockIdx.x * 128);
}

// ---------------------------------------------------------------------------
// Tensor-core flash attention, round 6:
//  - double-buffered K/V smem, software-pipelined gmem loads, 1 sync/tile
//  - K hi/lo interleaved as float4 per lane -> 1 LDS.128 per (kt,j)
//
// smem map (bytes):
//   buf b (b=0,1) at b*49152:
//     KP: 64 slots x 32 lanes x 16B = 32768   {kh_b0, kh_b1, kl_b0, kl_b1}
//     V : at +32768, 64 slots x 32 lanes x 8B = 16384
//   mask: 98304 + b*256 (64 floats each)
//   P   : 98816, 8 warps x 16 rows x 68 floats
// ---------------------------------------------------------------------------
#define ATTN_SMEM 133632
#define A_BUFSTRIDE 49152
#define A_VOFF 32768
#define A_MSK 98304
#define A_PO 98816
#define PSTRIDE 68
#define PWARP 4352

__global__ void __launch_bounds__(256, 1) attn_kernel(const int* __restrict__ mask) {
    extern __shared__ char smem[];
    const int tid = threadIdx.x;
    const int lane = tid & 31;
    const int w = tid >> 5;
    const int gid = lane >> 2;
    const int tig = lane & 3;

    const int bh = blockIdx.y;
    const int b = bh >> 4;
    const int h = bh & 15;
    const int qs_base = blockIdx.x * 128 + w * 16;

    const float* qbase = g_q + (size_t)bh * SS * DK;
    const float* kbase = g_k + (size_t)bh * SS * DK;
    const float* vbase = g_v + (size_t)bh * SS * DK;

    // ---- Q fragments (scale 1/8 folded in, hi/lo tf32 split), resident ----
    uint32_t qh[8][4], ql[8][4];
#pragma unroll
    for (int kt = 0; kt < 8; ++kt) {
#pragma unroll
        for (int e = 0; e < 4; ++e) {
            const int r = qs_base + gid + (e & 1) * 8;
            const int d = kt * 8 + tig + (e >> 1) * 4;
            const float x = qbase[(size_t)r * DK + d] * 0.125f;
            const uint32_t hb = f2tf32(x);
            qh[kt][e] = hb;
            ql[kt][e] = f2tf32(x - __uint_as_float(hb));
        }
    }

    float o[8][4];
#pragma unroll
    for (int j = 0; j < 8; ++j)
#pragma unroll
        for (int e = 0; e < 4; ++e) o[j][e] = 0.0f;
    float m0 = -1e30f, m1 = -1e30f, l0 = 0.0f, l1 = 0.0f;

    char* Pw = smem + A_PO + w * PWARP;

    // staging registers (pipelined): tile t data loaded during tile t-1
    float4 rk[4], rv[4];
    int rmask = 1;

    // prologue: LDG tile 0
#pragma unroll
    for (int i = 0; i < 4; ++i) {
        const int idx = tid + i * 256;
        const int row = idx >> 4, p4 = idx & 15;
        rk[i] = *(const float4*)(kbase + (size_t)row * DK + p4 * 4);
        rv[i] = *(const float4*)(vbase + (size_t)row * DK + p4 * 4);
    }
    if (tid < 64) rmask = mask[b * SS + tid];

    for (int t = 0; t < SS / 64; ++t) {
        const int buf = t & 1;
        char* kb = smem + buf * A_BUFSTRIDE;
        char* vb = kb + A_VOFF;

        // ---- STS staged tile t ----
#pragma unroll
        for (int i = 0; i < 4; ++i) {
            const int idx = tid + i * 256;
            const int row = idx >> 4, p4 = idx & 15;
            const float ke[4] = {rk[i].x, rk[i].y, rk[i].z, rk[i].w};
            const float ve[4] = {rv[i].x, rv[i].y, rv[i].z, rv[i].w};
#pragma unroll
            for (int e = 0; e < 4; ++e) {
                const int d = p4 * 4 + e;
                // K dest: slot(kt=d>>3, nt=row>>3), lane=(row&7)*4+(d&3)
                const int sbase = (((d >> 3) * 8 + (row >> 3)) << 9) +
                                  (((row & 7) * 4 + (d & 3)) << 4);
                const int khi = ((d >> 2) & 1) << 2;
                const uint32_t hb = f2tf32(ke[e]);
                *(uint32_t*)(kb + sbase + khi) = hb;
                *(uint32_t*)(kb + sbase + 8 + khi) =
                    f2tf32(ke[e] - __uint_as_float(hb));
                // V dest: slot(kt=row>>3, nt=d>>3), lane=(d&7)*4+(row&3), half=(row>>2)&1
                const int vbyte = (((row >> 3) * 8 + (d >> 3)) << 8) +
                                  ((d & 7) << 5) + ((row & 3) << 3) +
                                  (((row >> 2) & 1) << 2);
                *(uint32_t*)(vb + vbyte) = f2tf32(ve[e]);
            }
        }
        if (tid < 64)
            *(float*)(smem + A_MSK + buf * 256 + tid * 4) = rmask ? 0.0f : -1e9f;

        // ---- LDG tile t+1 (latency hidden under compute of tile t) ----
        if (t + 1 < SS / 64) {
            const int key0n = (t + 1) * 64;
#pragma unroll
            for (int i = 0; i < 4; ++i) {
                const int idx = tid + i * 256;
                const int row = idx >> 4, p4 = idx & 15;
                rk[i] = *(const float4*)(kbase + (size_t)(key0n + row) * DK + p4 * 4);
                rv[i] = *(const float4*)(vbase + (size_t)(key0n + row) * DK + p4 * 4);
            }
            if (tid < 64) rmask = mask[b * SS + key0n + tid];
        }
        __syncthreads();

        // ---- scores: S = (Q/8) K^T via 3xTF32 ----
        float sc[8][4];
#pragma unroll
        for (int j = 0; j < 8; ++j)
#pragma unroll
            for (int e = 0; e < 4; ++e) sc[j][e] = 0.0f;
#pragma unroll
        for (int kt = 0; kt < 8; ++kt) {
#pragma unroll
            for (int j = 0; j < 8; ++j) {
                const uint4 k4 = *(const uint4*)(kb + (((kt * 8 + j) << 9) +
                                                       (lane << 4)));
                uint32_t bhf[2] = {k4.x, k4.y};
                uint32_t blf[2] = {k4.z, k4.w};
                mma_tf32(sc[j], qh[kt], bhf);
                mma_tf32(sc[j], qh[kt], blf);
                mma_tf32(sc[j], ql[kt], bhf);
            }
        }

        // ---- mask, online softmax ----
        const char* mbuf = smem + A_MSK + buf * 256;
#pragma unroll
        for (int j = 0; j < 8; ++j) {
            const float2 ma = *(const float2*)(mbuf + (j * 8 + 2 * tig) * 4);
            sc[j][0] += ma.x; sc[j][1] += ma.y;
            sc[j][2] += ma.x; sc[j][3] += ma.y;
        }
        float rm0 = -1e30f, rm1 = -1e30f;
#pragma unroll
        for (int j = 0; j < 8; ++j) {
            rm0 = fmaxf(rm0, fmaxf(sc[j][0], sc[j][1]));
            rm1 = fmaxf(rm1, fmaxf(sc[j][2], sc[j][3]));
        }
        rm0 = fmaxf(rm0, __shfl_xor_sync(0xFFFFFFFF, rm0, 1));
        rm0 = fmaxf(rm0, __shfl_xor_sync(0xFFFFFFFF, rm0, 2));
        rm1 = fmaxf(rm1, __shfl_xor_sync(0xFFFFFFFF, rm1, 1));
        rm1 = fmaxf(rm1, __shfl_xor_sync(0xFFFFFFFF, rm1, 2));
        const float nm0 = fmaxf(m0, rm0), nm1 = fmaxf(m1, rm1);
        const float c0 = __expf(m0 - nm0), c1 = __expf(m1 - nm1);
        m0 = nm0; m1 = nm1;
        l0 *= c0; l1 *= c1;
#pragma unroll
        for (int j = 0; j < 8; ++j) {
            o[j][0] *= c0; o[j][1] *= c0;
            o[j][2] *= c1; o[j][3] *= c1;
        }
        float s0 = 0.0f, s1 = 0.0f;
#pragma unroll
        for (int j = 0; j < 8; ++j) {
            const float p0 = __expf(sc[j][0] - nm0);
            const float p1 = __expf(sc[j][1] - nm0);
            const float p2 = __expf(sc[j][2] - nm1);
            const float p3 = __expf(sc[j][3] - nm1);
            s0 += p0 + p1; s1 += p2 + p3;
            const int cb = j * 8 + 2 * tig;
            float2 v0 = {__uint_as_float(f2tf32(p0)), __uint_as_float(f2tf32(p1))};
            float2 v1 = {__uint_as_float(f2tf32(p2)), __uint_as_float(f2tf32(p3))};
            *(float2*)(Pw + (gid * PSTRIDE + cb) * 4) = v0;
            *(float2*)(Pw + ((gid + 8) * PSTRIDE + cb) * 4) = v1;
        }
        l0 += s0; l1 += s1;
        __syncwarp();

        // ---- O += P V (tf32) ----
#pragma unroll
        for (int kk = 0; kk < 8; ++kk) {
            uint32_t pa[4];
            pa[0] = *(const uint32_t*)(Pw + (gid * PSTRIDE + kk * 8 + tig) * 4);
            pa[1] = *(const uint32_t*)(Pw + ((gid + 8) * PSTRIDE + kk * 8 + tig) * 4);
            pa[2] = *(const uint32_t*)(Pw + (gid * PSTRIDE + kk * 8 + tig + 4) * 4);
            pa[3] = *(const uint32_t*)(Pw + ((gid + 8) * PSTRIDE + kk * 8 + tig + 4) * 4);
#pragma unroll
            for (int j = 0; j < 8; ++j) {
                uint32_t bvf[2];
                const uint2 bv2 =
                    *(const uint2*)(vb + (((kk * 8 + j) * 32 + lane) << 3));
                bvf[0] = bv2.x; bvf[1] = bv2.y;
                mma_tf32(o[j], pa, bvf);
            }
        }
        __syncwarp();
    }

    // ---- finalize ----
    float lt0 = l0, lt1 = l1;
    lt0 += __shfl_xor_sync(0xFFFFFFFF, lt0, 1);
    lt0 += __shfl_xor_sync(0xFFFFFFFF, lt0, 2);
    lt1 += __shfl_xor_sync(0xFFFFFFFF, lt1, 1);
    lt1 += __shfl_xor_sync(0xFFFFFFFF, lt1, 2);
    const float inv0 = 1.0f / lt0, inv1 = 1.0f / lt1;

    const int r0 = qs_base + gid, r1 = r0 + 8;
    float* o0 = g_ctx + ((size_t)(b * SS + r0)) * DD + h * DK;
    float* o1 = g_ctx + ((size_t)(b * SS + r1)) * DD + h * DK;
#pragma unroll
    for (int j = 0; j < 8; ++j) {
        const int cb = j * 8 + 2 * tig;
        float2 v0 = {o[j][0] * inv0, o[j][1] * inv0};
        float2 v1 = {o[j][2] * inv1, o[j][3] * inv1};
        *(float2*)(o0 + cb) = v0;
        *(float2*)(o1 + cb) = v1;
    }
}

// ---------------------------------------------------------------------------
// Inputs (metadata order): x, mask, Wq, bq, Wk, bk, Wv, bv, Wo, bo
// ---------------------------------------------------------------------------
extern "C" void kernel_launch(void* const* d_in, const int* in_sizes, int n_in,
                              void* d_out, int out_size) {
    const float* x  = (const float*)d_in[0];
    const int*   mk = (const int*)d_in[1];
    const float* Wq = (const float*)d_in[2];
    const float* bq = (const float*)d_in[3];
    const float* Wk = (const float*)d_in[4];
    const float* bk = (const float*)d_in[5];
    const float* Wv = (const float*)d_in[6];
    const float* bv = (const float*)d_in[7];
    const float* Wo = (const float*)d_in[8];
    const float* bo = (const float*)d_in[9];
    float* out = (float*)d_out;

    static bool configured = false;
    if (!configured) {
        cudaFuncSetAttribute(qkv_mm_kernel,
                             cudaFuncAttributeMaxDynamicSharedMemorySize,
                             MM_SMEM_BYTES);
        cudaFuncSetAttribute(oproj_mm_kernel,
                             cudaFuncAttributeMaxDynamicSharedMemorySize,
                             MM_SMEM_BYTES);
        cudaFuncSetAttribute(attn_kernel,
                             cudaFuncAttributeMaxDynamicSharedMemorySize,
                             ATTN_SMEM);
        configured = true;
    }

    // QKV projections (tf32 mma.sync), scattered to (B,H,S,DK)
    qkv_mm_kernel<<<dim3(DD / 128, MM / 128, 3), 256, MM_SMEM_BYTES>>>(
        x, Wq, bq, Wk, bk, Wv, bv);

    // Tensor-core flash attention (pipelined, double-buffered)
    attn_kernel<<<dim3(SS / 128, BB * HH), 256, ATTN_SMEM>>>(mk);

    // Output projection (tf32 mma.sync) -> d_out
    oproj_mm_kernel<<<dim3(DD / 128, MM / 128), 256, MM_SMEM_BYTES>>>(Wo, bo, out);
}

// round 7
// speedup vs baseline: 4.0232x; 1.4305x over previous
#include <cuda_runtime.h>
#include <cstdint>

// Problem constants (fixed by the dataset)
#define BB 2
#define SS 2048
#define DD 1024
#define HH 16
#define DK 64
#define MM (BB * SS)  // 4096 rows

// Scratch (allocation-free rule: __device__ globals)
__device__ float g_q[(size_t)BB * HH * SS * DK];    // (B,H,S,DK)
__device__ float g_k[(size_t)BB * HH * SS * DK];
__device__ float g_v[(size_t)BB * HH * SS * DK];
__device__ float g_ctx[(size_t)BB * SS * DD];       // (B,S,D)

// ---------------------------------------------------------------------------
// helpers (baseline sm_80+ ISA — no 'a'-suffix features)
// ---------------------------------------------------------------------------
__device__ __forceinline__ uint32_t f2tf32(float x) {
    uint32_t r;
    asm("cvt.rna.tf32.f32 %0, %1;" : "=r"(r) : "f"(x));
    return r;
}

__device__ __forceinline__ float ex2(float x) {
    float r;
    asm("ex2.approx.ftz.f32 %0, %1;" : "=f"(r) : "f"(x));
    return r;
}

__device__ __forceinline__ void mma_tf32(float c[4], const uint32_t a[4],
                                         const uint32_t b[2]) {
    asm volatile(
        "mma.sync.aligned.m16n8k8.row.col.f32.tf32.tf32.f32 "
        "{%0,%1,%2,%3}, {%4,%5,%6,%7}, {%8,%9}, {%0,%1,%2,%3};"
        : "+f"(c[0]), "+f"(c[1]), "+f"(c[2]), "+f"(c[3])
        : "r"(a[0]), "r"(a[1]), "r"(a[2]), "r"(a[3]), "r"(b[0]), "r"(b[1]));
}

// ---------------------------------------------------------------------------
// tf32 mma.sync GEMM: C[128,128] = A[128,1024] * W[128,1024]^T + bias
// 8 warps (2 m x 4 n), warp tile 64x32, BK=32, double-buffered smem,
// single __syncthreads per K-chunk. Fragment-packed smem with XOR-kt lane
// swizzle to kill STS bank conflicts.
// ---------------------------------------------------------------------------
#define MM_SMEM_BYTES 65536

template <bool SCATTER>
__device__ __forceinline__ void mm_core(const float* __restrict__ A,
                                        const float* __restrict__ W,
                                        const float* __restrict__ bias,
                                        float* __restrict__ out,
                                        int m0, int n0) {
    extern __shared__ char smem[];
    const int tid = threadIdx.x;
    const int lane = tid & 31;
    const int wid = tid >> 5;
    const int warp_m = wid & 1;
    const int warp_n = wid >> 1;

    float c[4][4][4];
#pragma unroll
    for (int i = 0; i < 4; i++)
#pragma unroll
        for (int j = 0; j < 4; j++)
#pragma unroll
            for (int e = 0; e < 4; e++) c[i][j][e] = 0.0f;

    const float* Abase = A + (size_t)m0 * DD;
    const float* Wbase = W + (size_t)n0 * DD;

    float4 av[4], bv[4];

#define STORE_STAGE(bufp)                                                     \
    do {                                                                      \
        char* sbA = smem + (bufp) * 32768;                                    \
        char* sbB = sbA + 16384;                                              \
        _Pragma("unroll") for (int i = 0; i < 4; i++) {                       \
            const int idx = tid + i * 256;                                    \
            const int row = idx >> 3, k4 = idx & 7;                           \
            const int kt = k4 >> 1, khi = k4 & 1;                             \
            const int mt = row >> 4, rm = row & 15;                           \
            const int slotA = kt * 8 + mt;                                    \
            const int elemA = (rm >> 3) + (khi << 1);                         \
            const int laneA0 = (rm & 7) * 4;                                  \
            const float ae[4] = {av[i].x, av[i].y, av[i].z, av[i].w};         \
            _Pragma("unroll") for (int e = 0; e < 4; e++)                     \
                *(uint32_t*)(sbA + ((slotA * 32 + ((laneA0 + e) ^ kt)) << 4)  \
                             + (elemA << 2)) = f2tf32(ae[e]);                 \
            const int nt = row >> 3, rn = row & 7;                            \
            const int slotB = kt * 16 + nt;                                   \
            const int laneB0 = rn * 4;                                        \
            const float be[4] = {bv[i].x, bv[i].y, bv[i].z, bv[i].w};         \
            _Pragma("unroll") for (int e = 0; e < 4; e++)                     \
                *(uint32_t*)(sbB + ((slotB * 32 + ((laneB0 + e) ^ kt)) << 3)  \
                             + (khi << 2)) = f2tf32(be[e]);                   \
        }                                                                     \
    } while (0)

#define LOAD_STAGE(c0)                                                        \
    do {                                                                      \
        _Pragma("unroll") for (int i = 0; i < 4; i++) {                       \
            const int idx = tid + i * 256;                                    \
            const int row = idx >> 3, k4 = idx & 7;                           \
            av[i] = *(const float4*)(Abase + (size_t)row * DD + (c0) + k4 * 4); \
            bv[i] = *(const float4*)(Wbase + (size_t)row * DD + (c0) + k4 * 4); \
        }                                                                     \
    } while (0)

    LOAD_STAGE(0);

    for (int ch = 0; ch < 32; ++ch) {
        const int buf = ch & 1;
        STORE_STAGE(buf);
        if (ch + 1 < 32) LOAD_STAGE((ch + 1) * 32);
        __syncthreads();

        const char* sbA = smem + buf * 32768;
        const char* sbB = sbA + 16384;
#pragma unroll
        for (int kt = 0; kt < 4; ++kt) {
            uint32_t af[4][4];
            uint32_t bf[4][2];
#pragma unroll
            for (int i = 0; i < 4; ++i) {
                const float4 v = *(const float4*)(sbA +
                    (((kt * 8 + warp_m * 4 + i) * 32 + (lane ^ kt)) << 4));
                af[i][0] = __float_as_uint(v.x);
                af[i][1] = __float_as_uint(v.y);
                af[i][2] = __float_as_uint(v.z);
                af[i][3] = __float_as_uint(v.w);
            }
#pragma unroll
            for (int j = 0; j < 4; ++j) {
                const float2 v = *(const float2*)(sbB +
                    (((kt * 16 + warp_n * 4 + j) * 32 + (lane ^ kt)) << 3));
                bf[j][0] = __float_as_uint(v.x);
                bf[j][1] = __float_as_uint(v.y);
            }
#pragma unroll
            for (int i = 0; i < 4; ++i)
#pragma unroll
                for (int j = 0; j < 4; ++j) mma_tf32(c[i][j], af[i], bf[j]);
        }
    }

#pragma unroll
    for (int i = 0; i < 4; ++i) {
        const int r0 = m0 + warp_m * 64 + i * 16 + (lane >> 2);
#pragma unroll
        for (int j = 0; j < 4; ++j) {
            const int cb = n0 + warp_n * 32 + j * 8 + 2 * (lane & 3);
            const float b0 = bias[cb], b1 = bias[cb + 1];
            float2 lo = {c[i][j][0] + b0, c[i][j][1] + b1};
            float2 hi = {c[i][j][2] + b0, c[i][j][3] + b1};
            if (SCATTER) {
                const int h = cb >> 6, d = cb & 63;
                const int bA = r0 >> 11, s0 = r0 & 2047;
                float* p0 = out + (((size_t)(bA * HH + h)) * SS + s0) * DK + d;
                *(float2*)p0 = lo;
                const int r1 = r0 + 8;
                const int bB = r1 >> 11, s1 = r1 & 2047;
                float* p1 = out + (((size_t)(bB * HH + h)) * SS + s1) * DK + d;
                *(float2*)p1 = hi;
            } else {
                *(float2*)(out + (size_t)r0 * DD + cb) = lo;
                *(float2*)(out + (size_t)(r0 + 8) * DD + cb) = hi;
            }
        }
    }
#undef STORE_STAGE
#undef LOAD_STAGE
}

__global__ void __launch_bounds__(256) qkv_mm_kernel(
    const float* __restrict__ x,
    const float* __restrict__ Wq, const float* __restrict__ bq,
    const float* __restrict__ Wk, const float* __restrict__ bk,
    const float* __restrict__ Wv, const float* __restrict__ bv) {
    const int z = blockIdx.z;
    const float* W = (z == 0) ? Wq : (z == 1) ? Wk : Wv;
    const float* bias = (z == 0) ? bq : (z == 1) ? bk : bv;
    float* out = (z == 0) ? g_q : (z == 1) ? g_k : g_v;
    mm_core<true>(x, W, bias, out, blockIdx.y * 128, blockIdx.x * 128);
}

__global__ void __launch_bounds__(256) oproj_mm_kernel(
    const float* __restrict__ Wo, const float* __restrict__ bo,
    float* __restrict__ out) {
    mm_core<false>(g_ctx, Wo, bo, out, blockIdx.y * 128, blockIdx.x * 128);
}

// ---------------------------------------------------------------------------
// Tensor-core flash attention (pipelined, double-buffered, swizzled packs).
// Softmax runs in log2-domain (log2e folded into Q scale; raw ex2.approx).
//
// smem map (bytes):
//   buf b (b=0,1) at b*49152:
//     KP: 64 slots x 32 lanes x 16B = 32768   {kh_b0, kh_b1, kl_b0, kl_b1}
//     V : at +32768, 64 slots x 32 lanes x 8B = 16384
//   mask: 98304 + b*256 (64 floats each)
//   P   : 98816, 8 warps x 16 rows x 68 floats
// ---------------------------------------------------------------------------
#define ATTN_SMEM 133632
#define A_BUFSTRIDE 49152
#define A_VOFF 32768
#define A_MSK 98304
#define A_PO 98816
#define PSTRIDE 68
#define PWARP 4352
#define QSCALE (0.125f * 1.44269504088896f)   // (1/sqrt(DK)) * log2(e)

__global__ void __launch_bounds__(256, 1) attn_kernel(const int* __restrict__ mask) {
    extern __shared__ char smem[];
    const int tid = threadIdx.x;
    const int lane = tid & 31;
    const int w = tid >> 5;
    const int gid = lane >> 2;
    const int tig = lane & 3;

    const int bh = blockIdx.y;
    const int b = bh >> 4;
    const int h = bh & 15;
    const int qs_base = blockIdx.x * 128 + w * 16;

    const float* qbase = g_q + (size_t)bh * SS * DK;
    const float* kbase = g_k + (size_t)bh * SS * DK;
    const float* vbase = g_v + (size_t)bh * SS * DK;

    // ---- Q fragments (scale*log2e folded in, hi/lo tf32 split), resident ----
    uint32_t qh[8][4], ql[8][4];
#pragma unroll
    for (int kt = 0; kt < 8; ++kt) {
#pragma unroll
        for (int e = 0; e < 4; ++e) {
            const int r = qs_base + gid + (e & 1) * 8;
            const int d = kt * 8 + tig + (e >> 1) * 4;
            const float x = qbase[(size_t)r * DK + d] * QSCALE;
            const uint32_t hb = f2tf32(x);
            qh[kt][e] = hb;
            ql[kt][e] = f2tf32(x - __uint_as_float(hb));
        }
    }

    float o[8][4];
#pragma unroll
    for (int j = 0; j < 8; ++j)
#pragma unroll
        for (int e = 0; e < 4; ++e) o[j][e] = 0.0f;
    float m0 = -1e30f, m1 = -1e30f, l0 = 0.0f, l1 = 0.0f;

    char* Pw = smem + A_PO + w * PWARP;

    // staging registers (pipelined): tile t data loaded during tile t-1
    float4 rk[4], rv[4];
    int rmask = 1;

    // prologue: LDG tile 0
#pragma unroll
    for (int i = 0; i < 4; ++i) {
        const int idx = tid + i * 256;
        const int row = idx >> 4, p4 = idx & 15;
        rk[i] = *(const float4*)(kbase + (size_t)row * DK + p4 * 4);
        rv[i] = *(const float4*)(vbase + (size_t)row * DK + p4 * 4);
    }
    if (tid < 64) rmask = mask[b * SS + tid];

    for (int t = 0; t < SS / 64; ++t) {
        const int buf = t & 1;
        char* kb = smem + buf * A_BUFSTRIDE;
        char* vb = kb + A_VOFF;

        // ---- STS staged tile t (XOR-swizzled lanes) ----
#pragma unroll
        for (int i = 0; i < 4; ++i) {
            const int idx = tid + i * 256;
            const int row = idx >> 4, p4 = idx & 15;
            const float ke[4] = {rk[i].x, rk[i].y, rk[i].z, rk[i].w};
            const float ve[4] = {rv[i].x, rv[i].y, rv[i].z, rv[i].w};
#pragma unroll
            for (int e = 0; e < 4; ++e) {
                const int d = p4 * 4 + e;
                const int dt = d >> 3;
                // K: slot(dt, row>>3), lane ((row&7)*4+(d&3)) ^ dt
                const int slotK = dt * 8 + (row >> 3);
                const int laneK = (((row & 7) * 4 + (d & 3)) ^ dt);
                const int khi = (d >> 2) & 1;
                char* kdst = kb + ((slotK * 32 + laneK) << 4) + (khi << 2);
                const uint32_t hb = f2tf32(ke[e]);
                *(uint32_t*)(kdst) = hb;
                *(uint32_t*)(kdst + 8) = f2tf32(ke[e] - __uint_as_float(hb));
                // V: slot(row>>3, dt), lane ((d&7)*4+(row&3)) ^ (dt<<1)
                const int slotV = (row >> 3) * 8 + dt;
                const int laneV = (((d & 7) * 4 + (row & 3)) ^ (dt << 1));
                const int half = (row >> 2) & 1;
                *(uint32_t*)(vb + ((slotV * 32 + laneV) << 3) + (half << 2)) =
                    f2tf32(ve[e]);
            }
        }
        if (tid < 64)
            *(float*)(smem + A_MSK + buf * 256 + tid * 4) = rmask ? 0.0f : -1e9f;

        // ---- LDG tile t+1 (latency hidden under compute of tile t) ----
        if (t + 1 < SS / 64) {
            const int key0n = (t + 1) * 64;
#pragma unroll
            for (int i = 0; i < 4; ++i) {
                const int idx = tid + i * 256;
                const int row = idx >> 4, p4 = idx & 15;
                rk[i] = *(const float4*)(kbase + (size_t)(key0n + row) * DK + p4 * 4);
                rv[i] = *(const float4*)(vbase + (size_t)(key0n + row) * DK + p4 * 4);
            }
            if (tid < 64) rmask = mask[b * SS + key0n + tid];
        }
        __syncthreads();

        // ---- scores (log2-domain): S = Q K^T via 3xTF32 ----
        float sc[8][4];
#pragma unroll
        for (int j = 0; j < 8; ++j)
#pragma unroll
            for (int e = 0; e < 4; ++e) sc[j][e] = 0.0f;
#pragma unroll
        for (int kt = 0; kt < 8; ++kt) {
#pragma unroll
            for (int j = 0; j < 8; ++j) {
                const uint4 k4v = *(const uint4*)(kb + (((kt * 8 + j) << 9) +
                                                       ((lane ^ kt) << 4)));
                uint32_t bhf[2] = {k4v.x, k4v.y};
                uint32_t blf[2] = {k4v.z, k4v.w};
                mma_tf32(sc[j], qh[kt], bhf);
                mma_tf32(sc[j], qh[kt], blf);
                mma_tf32(sc[j], ql[kt], bhf);
            }
        }

        // ---- mask, online softmax (log2-domain) ----
        const char* mbuf = smem + A_MSK + buf * 256;
#pragma unroll
        for (int j = 0; j < 8; ++j) {
            const float2 ma = *(const float2*)(mbuf + (j * 8 + 2 * tig) * 4);
            sc[j][0] += ma.x; sc[j][1] += ma.y;
            sc[j][2] += ma.x; sc[j][3] += ma.y;
        }
        float rm0 = -1e30f, rm1 = -1e30f;
#pragma unroll
        for (int j = 0; j < 8; ++j) {
            rm0 = fmaxf(rm0, fmaxf(sc[j][0], sc[j][1]));
            rm1 = fmaxf(rm1, fmaxf(sc[j][2], sc[j][3]));
        }
        rm0 = fmaxf(rm0, __shfl_xor_sync(0xFFFFFFFF, rm0, 1));
        rm0 = fmaxf(rm0, __shfl_xor_sync(0xFFFFFFFF, rm0, 2));
        rm1 = fmaxf(rm1, __shfl_xor_sync(0xFFFFFFFF, rm1, 1));
        rm1 = fmaxf(rm1, __shfl_xor_sync(0xFFFFFFFF, rm1, 2));
        const float nm0 = fmaxf(m0, rm0), nm1 = fmaxf(m1, rm1);
        const float c0 = ex2(m0 - nm0), c1 = ex2(m1 - nm1);
        m0 = nm0; m1 = nm1;
        l0 *= c0; l1 *= c1;
#pragma unroll
        for (int j = 0; j < 8; ++j) {
            o[j][0] *= c0; o[j][1] *= c0;
            o[j][2] *= c1; o[j][3] *= c1;
        }
        float s0 = 0.0f, s1 = 0.0f;
#pragma unroll
        for (int j = 0; j < 8; ++j) {
            const float p0 = ex2(sc[j][0] - nm0);
            const float p1 = ex2(sc[j][1] - nm0);
            const float p2 = ex2(sc[j][2] - nm1);
            const float p3 = ex2(sc[j][3] - nm1);
            s0 += p0 + p1; s1 += p2 + p3;
            const int cb = j * 8 + 2 * tig;
            float2 v0 = {__uint_as_float(f2tf32(p0)), __uint_as_float(f2tf32(p1))};
            float2 v1 = {__uint_as_float(f2tf32(p2)), __uint_as_float(f2tf32(p3))};
            *(float2*)(Pw + (gid * PSTRIDE + cb) * 4) = v0;
            *(float2*)(Pw + ((gid + 8) * PSTRIDE + cb) * 4) = v1;
        }
        l0 += s0; l1 += s1;
        __syncwarp();

        // ---- O += P V (tf32) ----
#pragma unroll
        for (int kk = 0; kk < 8; ++kk) {
            uint32_t pa[4];
            pa[0] = *(const uint32_t*)(Pw + (gid * PSTRIDE + kk * 8 + tig) * 4);
            pa[1] = *(const uint32_t*)(Pw + ((gid + 8) * PSTRIDE + kk * 8 + tig) * 4);
            pa[2] = *(const uint32_t*)(Pw + (gid * PSTRIDE + kk * 8 + tig + 4) * 4);
            pa[3] = *(const uint32_t*)(Pw + ((gid + 8) * PSTRIDE + kk * 8 + tig + 4) * 4);
#pragma unroll
            for (int j = 0; j < 8; ++j) {
                uint32_t bvf[2];
                const uint2 bv2 = *(const uint2*)(vb +
                    (((kk * 8 + j) * 32 + (lane ^ (j << 1))) << 3));
                bvf[0] = bv2.x; bvf[1] = bv2.y;
                mma_tf32(o[j], pa, bvf);
            }
        }
        __syncwarp();
    }

    // ---- finalize ----
    float lt0 = l0, lt1 = l1;
    lt0 += __shfl_xor_sync(0xFFFFFFFF, lt0, 1);
    lt0 += __shfl_xor_sync(0xFFFFFFFF, lt0, 2);
    lt1 += __shfl_xor_sync(0xFFFFFFFF, lt1, 1);
    lt1 += __shfl_xor_sync(0xFFFFFFFF, lt1, 2);
    const float inv0 = 1.0f / lt0, inv1 = 1.0f / lt1;

    const int r0 = qs_base + gid, r1 = r0 + 8;
    float* o0 = g_ctx + ((size_t)(b * SS + r0)) * DD + h * DK;
    float* o1 = g_ctx + ((size_t)(b * SS + r1)) * DD + h * DK;
#pragma unroll
    for (int j = 0; j < 8; ++j) {
        const int cb = j * 8 + 2 * tig;
        float2 v0 = {o[j][0] * inv0, o[j][1] * inv0};
        float2 v1 = {o[j][2] * inv1, o[j][3] * inv1};
        *(float2*)(o0 + cb) = v0;
        *(float2*)(o1 + cb) = v1;
    }
}

// ---------------------------------------------------------------------------
// Inputs (metadata order): x, mask, Wq, bq, Wk, bk, Wv, bv, Wo, bo
// ---------------------------------------------------------------------------
extern "C" void kernel_launch(void* const* d_in, const int* in_sizes, int n_in,
                              void* d_out, int out_size) {
    const float* x  = (const float*)d_in[0];
    const int*   mk = (const int*)d_in[1];
    const float* Wq = (const float*)d_in[2];
    const float* bq = (const float*)d_in[3];
    const float* Wk = (const float*)d_in[4];
    const float* bk = (const float*)d_in[5];
    const float* Wv = (const float*)d_in[6];
    const float* bv = (const float*)d_in[7];
    const float* Wo = (const float*)d_in[8];
    const float* bo = (const float*)d_in[9];
    float* out = (float*)d_out;

    static bool configured = false;
    if (!configured) {
        cudaFuncSetAttribute(qkv_mm_kernel,
                             cudaFuncAttributeMaxDynamicSharedMemorySize,
                             MM_SMEM_BYTES);
        cudaFuncSetAttribute(oproj_mm_kernel,
                             cudaFuncAttributeMaxDynamicSharedMemorySize,
                             MM_SMEM_BYTES);
        cudaFuncSetAttribute(attn_kernel,
                             cudaFuncAttributeMaxDynamicSharedMemorySize,
                             ATTN_SMEM);
        configured = true;
    }

    // QKV projections (tf32 mma.sync), scattered to (B,H,S,DK)
    qkv_mm_kernel<<<dim3(DD / 128, MM / 128, 3), 256, MM_SMEM_BYTES>>>(
        x, Wq, bq, Wk, bk, Wv, bv);

    // Tensor-core flash attention (pipelined, double-buffered, swizzled)
    attn_kernel<<<dim3(SS / 128, BB * HH), 256, ATTN_SMEM>>>(mk);

    // Output projection (tf32 mma.sync) -> d_out
    oproj_mm_kernel<<<dim3(DD / 128, MM / 128), 256, MM_SMEM_BYTES>>>(Wo, bo, out);
}

// round 8
// speedup vs baseline: 4.7997x; 1.1930x over previous
#include <cuda_runtime.h>
#include <cstdint>

// Problem constants (fixed by the dataset)
#define BB 2
#define SS 2048
#define DD 1024
#define HH 16
#define DK 64
#define MM (BB * SS)  // 4096 rows

// Scratch (allocation-free rule: __device__ globals)
__device__ float g_q[(size_t)BB * HH * SS * DK];    // (B,H,S,DK)
__device__ float g_k[(size_t)BB * HH * SS * DK];
__device__ float g_v[(size_t)BB * HH * SS * DK];
__device__ float g_ctx[(size_t)BB * SS * DD];       // (B,S,D)

// ---------------------------------------------------------------------------
// helpers (baseline sm_80+ ISA — no 'a'-suffix features)
// ---------------------------------------------------------------------------
__device__ __forceinline__ uint32_t f2tf32(float x) {
    uint32_t r;
    asm("cvt.rna.tf32.f32 %0, %1;" : "=r"(r) : "f"(x));
    return r;
}

__device__ __forceinline__ float ex2(float x) {
    float r;
    asm("ex2.approx.ftz.f32 %0, %1;" : "=f"(r) : "f"(x));
    return r;
}

// pack two floats to bf16x2: lo half = first arg, hi half = second arg
__device__ __forceinline__ uint32_t pack_bf16x2(float lo, float hi) {
    uint32_t r;
    asm("cvt.rn.bf16x2.f32 %0, %1, %2;" : "=r"(r) : "f"(hi), "f"(lo));
    return r;
}
__device__ __forceinline__ float bf16lo_f(uint32_t w) {
    return __uint_as_float(w << 16);
}
__device__ __forceinline__ float bf16hi_f(uint32_t w) {
    return __uint_as_float(w & 0xFFFF0000u);
}

__device__ __forceinline__ void mma_tf32(float c[4], const uint32_t a[4],
                                         const uint32_t b[2]) {
    asm volatile(
        "mma.sync.aligned.m16n8k8.row.col.f32.tf32.tf32.f32 "
        "{%0,%1,%2,%3}, {%4,%5,%6,%7}, {%8,%9}, {%0,%1,%2,%3};"
        : "+f"(c[0]), "+f"(c[1]), "+f"(c[2]), "+f"(c[3])
        : "r"(a[0]), "r"(a[1]), "r"(a[2]), "r"(a[3]), "r"(b[0]), "r"(b[1]));
}

__device__ __forceinline__ void mma_bf16(float c[4], const uint32_t a[4],
                                         const uint32_t b[2]) {
    asm volatile(
        "mma.sync.aligned.m16n8k16.row.col.f32.bf16.bf16.f32 "
        "{%0,%1,%2,%3}, {%4,%5,%6,%7}, {%8,%9}, {%0,%1,%2,%3};"
        : "+f"(c[0]), "+f"(c[1]), "+f"(c[2]), "+f"(c[3])
        : "r"(a[0]), "r"(a[1]), "r"(a[2]), "r"(a[3]), "r"(b[0]), "r"(b[1]));
}

// ---------------------------------------------------------------------------
// tf32 mma.sync GEMM: C[128,128] = A[128,1024] * W[128,1024]^T + bias
// (unchanged from round 7)
// ---------------------------------------------------------------------------
#define MM_SMEM_BYTES 65536

template <bool SCATTER>
__device__ __forceinline__ void mm_core(const float* __restrict__ A,
                                        const float* __restrict__ W,
                                        const float* __restrict__ bias,
                                        float* __restrict__ out,
                                        int m0, int n0) {
    extern __shared__ char smem[];
    const int tid = threadIdx.x;
    const int lane = tid & 31;
    const int wid = tid >> 5;
    const int warp_m = wid & 1;
    const int warp_n = wid >> 1;

    float c[4][4][4];
#pragma unroll
    for (int i = 0; i < 4; i++)
#pragma unroll
        for (int j = 0; j < 4; j++)
#pragma unroll
            for (int e = 0; e < 4; e++) c[i][j][e] = 0.0f;

    const float* Abase = A + (size_t)m0 * DD;
    const float* Wbase = W + (size_t)n0 * DD;

    float4 av[4], bv[4];

#define STORE_STAGE(bufp)                                                     \
    do {                                                                      \
        char* sbA = smem + (bufp) * 32768;                                    \
        char* sbB = sbA + 16384;                                              \
        _Pragma("unroll") for (int i = 0; i < 4; i++) {                       \
            const int idx = tid + i * 256;                                    \
            const int row = idx >> 3, k4 = idx & 7;                           \
            const int kt = k4 >> 1, khi = k4 & 1;                             \
            const int mt = row >> 4, rm = row & 15;                           \
            const int slotA = kt * 8 + mt;                                    \
            const int elemA = (rm >> 3) + (khi << 1);                         \
            const int laneA0 = (rm & 7) * 4;                                  \
            const float ae[4] = {av[i].x, av[i].y, av[i].z, av[i].w};         \
            _Pragma("unroll") for (int e = 0; e < 4; e++)                     \
                *(uint32_t*)(sbA + ((slotA * 32 + ((laneA0 + e) ^ kt)) << 4)  \
                             + (elemA << 2)) = f2tf32(ae[e]);                 \
            const int nt = row >> 3, rn = row & 7;                            \
            const int slotB = kt * 16 + nt;                                   \
            const int laneB0 = rn * 4;                                        \
            const float be[4] = {bv[i].x, bv[i].y, bv[i].z, bv[i].w};         \
            _Pragma("unroll") for (int e = 0; e < 4; e++)                     \
                *(uint32_t*)(sbB + ((slotB * 32 + ((laneB0 + e) ^ kt)) << 3)  \
                             + (khi << 2)) = f2tf32(be[e]);                   \
        }                                                                     \
    } while (0)

#define LOAD_STAGE(c0)                                                        \
    do {                                                                      \
        _Pragma("unroll") for (int i = 0; i < 4; i++) {                       \
            const int idx = tid + i * 256;                                    \
            const int row = idx >> 3, k4 = idx & 7;                           \
            av[i] = *(const float4*)(Abase + (size_t)row * DD + (c0) + k4 * 4); \
            bv[i] = *(const float4*)(Wbase + (size_t)row * DD + (c0) + k4 * 4); \
        }                                                                     \
    } while (0)

    LOAD_STAGE(0);

    for (int ch = 0; ch < 32; ++ch) {
        const int buf = ch & 1;
        STORE_STAGE(buf);
        if (ch + 1 < 32) LOAD_STAGE((ch + 1) * 32);
        __syncthreads();

        const char* sbA = smem + buf * 32768;
        const char* sbB = sbA + 16384;
#pragma unroll
        for (int kt = 0; kt < 4; ++kt) {
            uint32_t af[4][4];
            uint32_t bf[4][2];
#pragma unroll
            for (int i = 0; i < 4; ++i) {
                const float4 v = *(const float4*)(sbA +
                    (((kt * 8 + warp_m * 4 + i) * 32 + (lane ^ kt)) << 4));
                af[i][0] = __float_as_uint(v.x);
                af[i][1] = __float_as_uint(v.y);
                af[i][2] = __float_as_uint(v.z);
                af[i][3] = __float_as_uint(v.w);
            }
#pragma unroll
            for (int j = 0; j < 4; ++j) {
                const float2 v = *(const float2*)(sbB +
                    (((kt * 16 + warp_n * 4 + j) * 32 + (lane ^ kt)) << 3));
                bf[j][0] = __float_as_uint(v.x);
                bf[j][1] = __float_as_uint(v.y);
            }
#pragma unroll
            for (int i = 0; i < 4; ++i)
#pragma unroll
                for (int j = 0; j < 4; ++j) mma_tf32(c[i][j], af[i], bf[j]);
        }
    }

#pragma unroll
    for (int i = 0; i < 4; ++i) {
        const int r0 = m0 + warp_m * 64 + i * 16 + (lane >> 2);
#pragma unroll
        for (int j = 0; j < 4; ++j) {
            const int cb = n0 + warp_n * 32 + j * 8 + 2 * (lane & 3);
            const float b0 = bias[cb], b1 = bias[cb + 1];
            float2 lo = {c[i][j][0] + b0, c[i][j][1] + b1};
            float2 hi = {c[i][j][2] + b0, c[i][j][3] + b1};
            if (SCATTER) {
                const int h = cb >> 6, d = cb & 63;
                const int bA = r0 >> 11, s0 = r0 & 2047;
                float* p0 = out + (((size_t)(bA * HH + h)) * SS + s0) * DK + d;
                *(float2*)p0 = lo;
                const int r1 = r0 + 8;
                const int bB = r1 >> 11, s1 = r1 & 2047;
                float* p1 = out + (((size_t)(bB * HH + h)) * SS + s1) * DK + d;
                *(float2*)p1 = hi;
            } else {
                *(float2*)(out + (size_t)r0 * DD + cb) = lo;
                *(float2*)(out + (size_t)(r0 + 8) * DD + cb) = hi;
            }
        }
    }
#undef STORE_STAGE
#undef LOAD_STAGE
}

__global__ void __launch_bounds__(256) qkv_mm_kernel(
    const float* __restrict__ x,
    const float* __restrict__ Wq, const float* __restrict__ bq,
    const float* __restrict__ Wk, const float* __restrict__ bk,
    const float* __restrict__ Wv, const float* __restrict__ bv) {
    const int z = blockIdx.z;
    const float* W = (z == 0) ? Wq : (z == 1) ? Wk : Wv;
    const float* bias = (z == 0) ? bq : (z == 1) ? bk : bv;
    float* out = (z == 0) ? g_q : (z == 1) ? g_k : g_v;
    mm_core<true>(x, W, bias, out, blockIdx.y * 128, blockIdx.x * 128);
}

__global__ void __launch_bounds__(256) oproj_mm_kernel(
    const float* __restrict__ Wo, const float* __restrict__ bo,
    float* __restrict__ out) {
    mm_core<false>(g_ctx, Wo, bo, out, blockIdx.y * 128, blockIdx.x * 128);
}

// ---------------------------------------------------------------------------
// Tensor-core flash attention, round 8:
//  - QK^T via bf16 3-term m16n8k16 (hi/lo split of Q and K): half the mmas,
//    half the K smem/LDS vs tf32 3-term.
//  - PV stays tf32 single-pass. Log2-domain softmax (ex2).
//
// smem map (bytes):
//   buf b (b=0,1) at b*32768:
//     K : 32 slots (kt 0..3, j 0..7) x 32 lanes x 16B = 16384
//         per lane: {kh_b0, kh_b1, kl_b0, kl_b1} (bf16x2 each)
//     V : at +16384, 64 slots x 32 lanes x 8B = 16384 (tf32 pack)
//   mask: 65536 + b*256 (64 floats each)
//   P   : 66048, 8 warps x 16 rows x 68 floats
// ---------------------------------------------------------------------------
#define ATTN_SMEM 100864
#define A_BUFSTRIDE 32768
#define A_VOFF 16384
#define A_MSK 65536
#define A_PO 66048
#define PSTRIDE 68
#define PWARP 4352
#define QSCALE (0.125f * 1.44269504088896f)   // (1/sqrt(DK)) * log2(e)

__global__ void __launch_bounds__(256, 1) attn_kernel(const int* __restrict__ mask) {
    extern __shared__ char smem[];
    const int tid = threadIdx.x;
    const int lane = tid & 31;
    const int w = tid >> 5;
    const int gid = lane >> 2;
    const int tig = lane & 3;

    const int bh = blockIdx.y;
    const int b = bh >> 4;
    const int h = bh & 15;
    const int qs_base = blockIdx.x * 128 + w * 16;

    const float* qbase = g_q + (size_t)bh * SS * DK;
    const float* kbase = g_k + (size_t)bh * SS * DK;
    const float* vbase = g_v + (size_t)bh * SS * DK;

    // ---- Q fragments: bf16 hi/lo, m16n8k16 A layout, scale*log2e folded ----
    // qh[kt][r], ql[kt][r]: r0=(g, k lo-pair), r1=(g+8, lo), r2=(g, hi), r3=(g+8, hi)
    uint32_t qh[4][4], ql[4][4];
#pragma unroll
    for (int kt = 0; kt < 4; ++kt) {
#pragma unroll
        for (int r = 0; r < 4; ++r) {
            const int row = qs_base + gid + (r & 1) * 8;
            const int d = kt * 16 + 2 * tig + (r >> 1) * 8;
            const float2 qv = *(const float2*)(qbase + (size_t)row * DK + d);
            const float f0 = qv.x * QSCALE, f1 = qv.y * QSCALE;
            const uint32_t hw = pack_bf16x2(f0, f1);
            qh[kt][r] = hw;
            ql[kt][r] = pack_bf16x2(f0 - bf16lo_f(hw), f1 - bf16hi_f(hw));
        }
    }

    float o[8][4];
#pragma unroll
    for (int j = 0; j < 8; ++j)
#pragma unroll
        for (int e = 0; e < 4; ++e) o[j][e] = 0.0f;
    float m0 = -1e30f, m1 = -1e30f, l0 = 0.0f, l1 = 0.0f;

    char* Pw = smem + A_PO + w * PWARP;

    // staging registers (pipelined): tile t data loaded during tile t-1
    float4 rk[4], rv[4];
    int rmask = 1;

    // prologue: LDG tile 0
#pragma unroll
    for (int i = 0; i < 4; ++i) {
        const int idx = tid + i * 256;
        const int row = idx >> 4, p4 = idx & 15;
        rk[i] = *(const float4*)(kbase + (size_t)row * DK + p4 * 4);
        rv[i] = *(const float4*)(vbase + (size_t)row * DK + p4 * 4);
    }
    if (tid < 64) rmask = mask[b * SS + tid];

    for (int t = 0; t < SS / 64; ++t) {
        const int buf = t & 1;
        char* kb = smem + buf * A_BUFSTRIDE;
        char* vb = kb + A_VOFF;

        // ---- STS staged tile t ----
#pragma unroll
        for (int i = 0; i < 4; ++i) {
            const int idx = tid + i * 256;
            const int row = idx >> 4, p4 = idx & 15;
            const float ke[4] = {rk[i].x, rk[i].y, rk[i].z, rk[i].w};
            const float ve[4] = {rv[i].x, rv[i].y, rv[i].z, rv[i].w};
            // K: bf16 hi/lo pairs. For ep=0,1: d0 = p4*4 + ep*2 (two elems)
#pragma unroll
            for (int ep = 0; ep < 2; ++ep) {
                const int d0 = p4 * 4 + ep * 2;
                const int kt = d0 >> 4, dd = d0 & 15;
                const int reg = dd >> 3, quad = (dd >> 1) & 3;
                const int laneK = (((row & 7) * 4 + quad) ^ kt);
                char* base = kb + (((kt * 8 + (row >> 3)) * 32 + laneK) << 4)
                             + (reg << 2);
                const float f0 = ke[ep * 2], f1 = ke[ep * 2 + 1];
                const uint32_t hw = pack_bf16x2(f0, f1);
                *(uint32_t*)(base) = hw;
                *(uint32_t*)(base + 8) =
                    pack_bf16x2(f0 - bf16lo_f(hw), f1 - bf16hi_f(hw));
            }
            // V: tf32 pack (unchanged layout)
#pragma unroll
            for (int e = 0; e < 4; ++e) {
                const int d = p4 * 4 + e;
                const int dt = d >> 3;
                const int slotV = (row >> 3) * 8 + dt;
                const int laneV = (((d & 7) * 4 + (row & 3)) ^ (dt << 1));
                const int half = (row >> 2) & 1;
                *(uint32_t*)(vb + ((slotV * 32 + laneV) << 3) + (half << 2)) =
                    f2tf32(ve[e]);
            }
        }
        if (tid < 64)
            *(float*)(smem + A_MSK + buf * 256 + tid * 4) = rmask ? 0.0f : -1e9f;

        // ---- LDG tile t+1 (latency hidden under compute of tile t) ----
        if (t + 1 < SS / 64) {
            const int key0n = (t + 1) * 64;
#pragma unroll
            for (int i = 0; i < 4; ++i) {
                const int idx = tid + i * 256;
                const int row = idx >> 4, p4 = idx & 15;
                rk[i] = *(const float4*)(kbase + (size_t)(key0n + row) * DK + p4 * 4);
                rv[i] = *(const float4*)(vbase + (size_t)(key0n + row) * DK + p4 * 4);
            }
            if (tid < 64) rmask = mask[b * SS + key0n + tid];
        }
        __syncthreads();

        // ---- scores (log2-domain): S = Q K^T via bf16 3-term ----
        float sc[8][4];
#pragma unroll
        for (int j = 0; j < 8; ++j)
#pragma unroll
            for (int e = 0; e < 4; ++e) sc[j][e] = 0.0f;
#pragma unroll
        for (int kt = 0; kt < 4; ++kt) {
#pragma unroll
            for (int j = 0; j < 8; ++j) {
                const uint4 k4v = *(const uint4*)(kb + (((kt * 8 + j) << 9) +
                                                       ((lane ^ kt) << 4)));
                uint32_t kh2[2] = {k4v.x, k4v.y};
                uint32_t kl2[2] = {k4v.z, k4v.w};
                mma_bf16(sc[j], qh[kt], kh2);
                mma_bf16(sc[j], qh[kt], kl2);
                mma_bf16(sc[j], ql[kt], kh2);
            }
        }

        // ---- mask, online softmax (log2-domain) ----
        const char* mbuf = smem + A_MSK + buf * 256;
#pragma unroll
        for (int j = 0; j < 8; ++j) {
            const float2 ma = *(const float2*)(mbuf + (j * 8 + 2 * tig) * 4);
            sc[j][0] += ma.x; sc[j][1] += ma.y;
            sc[j][2] += ma.x; sc[j][3] += ma.y;
        }
        float rm0 = -1e30f, rm1 = -1e30f;
#pragma unroll
        for (int j = 0; j < 8; ++j) {
            rm0 = fmaxf(rm0, fmaxf(sc[j][0], sc[j][1]));
            rm1 = fmaxf(rm1, fmaxf(sc[j][2], sc[j][3]));
        }
        rm0 = fmaxf(rm0, __shfl_xor_sync(0xFFFFFFFF, rm0, 1));
        rm0 = fmaxf(rm0, __shfl_xor_sync(0xFFFFFFFF, rm0, 2));
        rm1 = fmaxf(rm1, __shfl_xor_sync(0xFFFFFFFF, rm1, 1));
        rm1 = fmaxf(rm1, __shfl_xor_sync(0xFFFFFFFF, rm1, 2));
        const float nm0 = fmaxf(m0, rm0), nm1 = fmaxf(m1, rm1);
        const float c0 = ex2(m0 - nm0), c1 = ex2(m1 - nm1);
        m0 = nm0; m1 = nm1;
        l0 *= c0; l1 *= c1;
#pragma unroll
        for (int j = 0; j < 8; ++j) {
            o[j][0] *= c0; o[j][1] *= c0;
            o[j][2] *= c1; o[j][3] *= c1;
        }
        float s0 = 0.0f, s1 = 0.0f;
#pragma unroll
        for (int j = 0; j < 8; ++j) {
            const float p0 = ex2(sc[j][0] - nm0);
            const float p1 = ex2(sc[j][1] - nm0);
            const float p2 = ex2(sc[j][2] - nm1);
            const float p3 = ex2(sc[j][3] - nm1);
            s0 += p0 + p1; s1 += p2 + p3;
            const int cb = j * 8 + 2 * tig;
            float2 v0 = {__uint_as_float(f2tf32(p0)), __uint_as_float(f2tf32(p1))};
            float2 v1 = {__uint_as_float(f2tf32(p2)), __uint_as_float(f2tf32(p3))};
            *(float2*)(Pw + (gid * PSTRIDE + cb) * 4) = v0;
            *(float2*)(Pw + ((gid + 8) * PSTRIDE + cb) * 4) = v1;
        }
        l0 += s0; l1 += s1;
        __syncwarp();

        // ---- O += P V (tf32) ----
#pragma unroll
        for (int kk = 0; kk < 8; ++kk) {
            uint32_t pa[4];
            pa[0] = *(const uint32_t*)(Pw + (gid * PSTRIDE + kk * 8 + tig) * 4);
            pa[1] = *(const uint32_t*)(Pw + ((gid + 8) * PSTRIDE + kk * 8 + tig) * 4);
            pa[2] = *(const uint32_t*)(Pw + (gid * PSTRIDE + kk * 8 + tig + 4) * 4);
            pa[3] = *(const uint32_t*)(Pw + ((gid + 8) * PSTRIDE + kk * 8 + tig + 4) * 4);
#pragma unroll
            for (int j = 0; j < 8; ++j) {
                uint32_t bvf[2];
                const uint2 bv2 = *(const uint2*)(vb +
                    (((kk * 8 + j) * 32 + (lane ^ (j << 1))) << 3));
                bvf[0] = bv2.x; bvf[1] = bv2.y;
                mma_tf32(o[j], pa, bvf);
            }
        }
        __syncwarp();
    }

    // ---- finalize ----
    float lt0 = l0, lt1 = l1;
    lt0 += __shfl_xor_sync(0xFFFFFFFF, lt0, 1);
    lt0 += __shfl_xor_sync(0xFFFFFFFF, lt0, 2);
    lt1 += __shfl_xor_sync(0xFFFFFFFF, lt1, 1);
    lt1 += __shfl_xor_sync(0xFFFFFFFF, lt1, 2);
    const float inv0 = 1.0f / lt0, inv1 = 1.0f / lt1;

    const int r0 = qs_base + gid, r1 = r0 + 8;
    float* o0 = g_ctx + ((size_t)(b * SS + r0)) * DD + h * DK;
    float* o1 = g_ctx + ((size_t)(b * SS + r1)) * DD + h * DK;
#pragma unroll
    for (int j = 0; j < 8; ++j) {
        const int cb = j * 8 + 2 * tig;
        float2 v0 = {o[j][0] * inv0, o[j][1] * inv0};
        float2 v1 = {o[j][2] * inv1, o[j][3] * inv1};
        *(float2*)(o0 + cb) = v0;
        *(float2*)(o1 + cb) = v1;
    }
}

// ---------------------------------------------------------------------------
// Inputs (metadata order): x, mask, Wq, bq, Wk, bk, Wv, bv, Wo, bo
// ---------------------------------------------------------------------------
extern "C" void kernel_launch(void* const* d_in, const int* in_sizes, int n_in,
                              void* d_out, int out_size) {
    const float* x  = (const float*)d_in[0];
    const int*   mk = (const int*)d_in[1];
    const float* Wq = (const float*)d_in[2];
    const float* bq = (const float*)d_in[3];
    const float* Wk = (const float*)d_in[4];
    const float* bk = (const float*)d_in[5];
    const float* Wv = (const float*)d_in[6];
    const float* bv = (const float*)d_in[7];
    const float* Wo = (const float*)d_in[8];
    const float* bo = (const float*)d_in[9];
    float* out = (float*)d_out;

    static bool configured = false;
    if (!configured) {
        cudaFuncSetAttribute(qkv_mm_kernel,
                             cudaFuncAttributeMaxDynamicSharedMemorySize,
                             MM_SMEM_BYTES);
        cudaFuncSetAttribute(oproj_mm_kernel,
                             cudaFuncAttributeMaxDynamicSharedMemorySize,
                             MM_SMEM_BYTES);
        cudaFuncSetAttribute(attn_kernel,
                             cudaFuncAttributeMaxDynamicSharedMemorySize,
                             ATTN_SMEM);
        configured = true;
    }

    // QKV projections (tf32 mma.sync), scattered to (B,H,S,DK)
    qkv_mm_kernel<<<dim3(DD / 128, MM / 128, 3), 256, MM_SMEM_BYTES>>>(
        x, Wq, bq, Wk, bk, Wv, bv);

    // Tensor-core flash attention (bf16 QK, tf32 PV)
    attn_kernel<<<dim3(SS / 128, BB * HH), 256, ATTN_SMEM>>>(mk);

    // Output projection (tf32 mma.sync) -> d_out
    oproj_mm_kernel<<<dim3(DD / 128, MM / 128), 256, MM_SMEM_BYTES>>>(Wo, bo, out);
}